// round 2
// baseline (speedup 1.0000x reference)
#include <cuda_runtime.h>
#include <math.h>

#define S_LEN 2048
#define B_SZ  4
#define E_DIM 512
#define H_NUM 8
#define HD    64
#define M_ROWS (S_LEN * B_SZ)   // 8192

// Scratch (allocation-free rule: __device__ globals)
__device__ float g_qp[B_SZ * H_NUM * S_LEN * HD];   // (b*H+h, s, d), q pre-scaled by 1/8
__device__ float g_kp[B_SZ * H_NUM * S_LEN * HD];
__device__ float g_vp[B_SZ * H_NUM * S_LEN * HD];
__device__ float g_ctx[M_ROWS * E_DIM];             // (s*B+b, e) attention output

// ---------------------------------------------------------------------------
// QKV projection: C = X @ W^T + bias (optionally scaled), scattered to
// head-major layout. z=0: q (scale 1/8), z=1: k, z=2: v (weight rows 2E:3E).
// Tile: BM=BN=64, BK=16, 256 threads, 4x4 micro-tile per thread.
// ---------------------------------------------------------------------------
__global__ __launch_bounds__(256) void qkv_proj_kernel(
    const float* __restrict__ query, const float* __restrict__ key,
    const float* __restrict__ value, const float* __restrict__ W,
    const float* __restrict__ bias)
{
    const int z = blockIdx.z;
    const float* X  = (z == 0) ? query : (z == 1) ? key : value;
    const float* Wz = W    + ((z == 2) ? 2 * E_DIM * E_DIM : 0);
    const float* bz = bias + ((z == 2) ? 2 * E_DIM : 0);
    float* out      = (z == 0) ? g_qp : (z == 1) ? g_kp : g_vp;
    const float scale = (z == 0) ? 0.125f : 1.0f;

    __shared__ __align__(16) float Xs[16][64];
    __shared__ __align__(16) float Ws[16][64];

    const int mBase = blockIdx.x * 64;
    const int nBase = blockIdx.y * 64;
    const int t  = threadIdx.x;
    const int tx = t & 15;
    const int ty = t >> 4;

    float acc[4][4];
#pragma unroll
    for (int i = 0; i < 4; i++)
#pragma unroll
        for (int j = 0; j < 4; j++) acc[i][j] = 0.0f;

    const int lm = t >> 2;         // 0..63 row within tile
    const int lk = (t & 3) << 2;   // 0,4,8,12

    for (int k0 = 0; k0 < E_DIM; k0 += 16) {
        float4 xv = *(const float4*)(X  + (mBase + lm) * E_DIM + k0 + lk);
        float4 wv = *(const float4*)(Wz + (nBase + lm) * E_DIM + k0 + lk);
        Xs[lk + 0][lm] = xv.x; Xs[lk + 1][lm] = xv.y;
        Xs[lk + 2][lm] = xv.z; Xs[lk + 3][lm] = xv.w;
        Ws[lk + 0][lm] = wv.x; Ws[lk + 1][lm] = wv.y;
        Ws[lk + 2][lm] = wv.z; Ws[lk + 3][lm] = wv.w;
        __syncthreads();
#pragma unroll
        for (int kk = 0; kk < 16; kk++) {
            float4 a = *(const float4*)&Xs[kk][ty * 4];
            float4 b = *(const float4*)&Ws[kk][tx * 4];
            float av[4] = {a.x, a.y, a.z, a.w};
            float bv[4] = {b.x, b.y, b.z, b.w};
#pragma unroll
            for (int i = 0; i < 4; i++)
#pragma unroll
                for (int j = 0; j < 4; j++)
                    acc[i][j] = fmaf(av[i], bv[j], acc[i][j]);
        }
        __syncthreads();
    }

    // Epilogue: bias + scale, scatter to (b*H+h, s, d)
    const int n0 = nBase + tx * 4;
    const int h_ = n0 >> 6;        // head
    const int d0 = n0 & 63;        // dim within head (tile never crosses a head)
    const float4 bvec = *(const float4*)(bz + n0);
#pragma unroll
    for (int i = 0; i < 4; i++) {
        const int m  = mBase + ty * 4 + i;
        const int s_ = m >> 2;     // m = s*B + b, B=4
        const int b_ = m & 3;
        float4 o;
        o.x = (acc[i][0] + bvec.x) * scale;
        o.y = (acc[i][1] + bvec.y) * scale;
        o.z = (acc[i][2] + bvec.z) * scale;
        o.w = (acc[i][3] + bvec.w) * scale;
        *(float4*)(out + ((size_t)(b_ * H_NUM + h_) * S_LEN + s_) * HD + d0) = o;
    }
}

// ---------------------------------------------------------------------------
// Flash attention: one block per (head, 64-query tile). 128 threads:
// 2 threads per query row, each owning 32 of the 64 head dims.
// Online softmax, K/V streamed through smem in 64-key tiles.
// ---------------------------------------------------------------------------
__global__ __launch_bounds__(128) void attn_kernel()
{
    const int bh = blockIdx.y;     // b*H + h
    const int qt = blockIdx.x;
    const int t  = threadIdx.x;
    const int r    = t >> 1;       // query row within tile: 0..63
    const int half = t & 1;        // which 32-dim half

    const float* qrow = g_qp + ((size_t)bh * S_LEN + qt * 64 + r) * HD + half * 32;
    float q[32];
#pragma unroll
    for (int d = 0; d < 32; d++) q[d] = qrow[d];

    float o[32];
#pragma unroll
    for (int d = 0; d < 32; d++) o[d] = 0.0f;
    float mval = -1e30f;
    float lsum = 0.0f;

    __shared__ __align__(16) float Ks[64][64];
    __shared__ __align__(16) float Vs[64][64];

    const float* kbase = g_kp + (size_t)bh * S_LEN * HD;
    const float* vbase = g_vp + (size_t)bh * S_LEN * HD;

    for (int kt = 0; kt < S_LEN / 64; kt++) {
        __syncthreads();   // protect previous-iteration smem reads
        const float4* ksrc = (const float4*)(kbase + (size_t)kt * 64 * HD);
        const float4* vsrc = (const float4*)(vbase + (size_t)kt * 64 * HD);
        float4* kd = (float4*)&Ks[0][0];
        float4* vd = (float4*)&Vs[0][0];
#pragma unroll
        for (int i = 0; i < 8; i++) {
            kd[t + i * 128] = ksrc[t + i * 128];
            vd[t + i * 128] = vsrc[t + i * 128];
        }
        __syncthreads();

        float sreg[64];
#pragma unroll
        for (int j = 0; j < 64; j++) {
            float a = 0.0f;
            const float* kr = &Ks[j][half * 32];
#pragma unroll
            for (int d = 0; d < 32; d++) a = fmaf(q[d], kr[d], a);
            a += __shfl_xor_sync(0xffffffffu, a, 1);   // combine the two halves
            sreg[j] = a;
        }

        float mt = mval;
#pragma unroll
        for (int j = 0; j < 64; j++) mt = fmaxf(mt, sreg[j]);
        const float alpha = __expf(mval - mt);
        mval = mt;
        lsum *= alpha;
#pragma unroll
        for (int d = 0; d < 32; d++) o[d] *= alpha;

#pragma unroll
        for (int j = 0; j < 64; j++) {
            const float p = __expf(sreg[j] - mt);
            lsum += p;
            const float* vr = &Vs[j][half * 32];
#pragma unroll
            for (int d = 0; d < 32; d++) o[d] = fmaf(p, vr[d], o[d]);
        }
    }

    const float inv = 1.0f / lsum;
    const int b_ = bh >> 3;
    const int h_ = bh & 7;
    const int s_ = qt * 64 + r;
    float* dst = g_ctx + ((size_t)s_ * B_SZ + b_) * E_DIM + h_ * HD + half * 32;
#pragma unroll
    for (int d = 0; d < 32; d += 4) {
        float4 v4 = {o[d] * inv, o[d + 1] * inv, o[d + 2] * inv, o[d + 3] * inv};
        *(float4*)(dst + d) = v4;
    }
}

// ---------------------------------------------------------------------------
// Output projection: out = ctx @ Wo^T + bo, row-major (s*B+b, e) = (S,B,E)
// ---------------------------------------------------------------------------
__global__ __launch_bounds__(256) void out_proj_kernel(
    const float* __restrict__ Wo, const float* __restrict__ bo,
    float* __restrict__ out)
{
    __shared__ __align__(16) float Xs[16][64];
    __shared__ __align__(16) float Ws[16][64];

    const int mBase = blockIdx.x * 64;
    const int nBase = blockIdx.y * 64;
    const int t  = threadIdx.x;
    const int tx = t & 15;
    const int ty = t >> 4;

    float acc[4][4];
#pragma unroll
    for (int i = 0; i < 4; i++)
#pragma unroll
        for (int j = 0; j < 4; j++) acc[i][j] = 0.0f;

    const int lm = t >> 2;
    const int lk = (t & 3) << 2;

    for (int k0 = 0; k0 < E_DIM; k0 += 16) {
        float4 xv = *(const float4*)(g_ctx + (size_t)(mBase + lm) * E_DIM + k0 + lk);
        float4 wv = *(const float4*)(Wo    + (size_t)(nBase + lm) * E_DIM + k0 + lk);
        Xs[lk + 0][lm] = xv.x; Xs[lk + 1][lm] = xv.y;
        Xs[lk + 2][lm] = xv.z; Xs[lk + 3][lm] = xv.w;
        Ws[lk + 0][lm] = wv.x; Ws[lk + 1][lm] = wv.y;
        Ws[lk + 2][lm] = wv.z; Ws[lk + 3][lm] = wv.w;
        __syncthreads();
#pragma unroll
        for (int kk = 0; kk < 16; kk++) {
            float4 a = *(const float4*)&Xs[kk][ty * 4];
            float4 b = *(const float4*)&Ws[kk][tx * 4];
            float av[4] = {a.x, a.y, a.z, a.w};
            float bv[4] = {b.x, b.y, b.z, b.w};
#pragma unroll
            for (int i = 0; i < 4; i++)
#pragma unroll
                for (int j = 0; j < 4; j++)
                    acc[i][j] = fmaf(av[i], bv[j], acc[i][j]);
        }
        __syncthreads();
    }

    const int n0 = nBase + tx * 4;
    const float4 bvec = *(const float4*)(bo + n0);
#pragma unroll
    for (int i = 0; i < 4; i++) {
        const int m = mBase + ty * 4 + i;
        float4 o;
        o.x = acc[i][0] + bvec.x;
        o.y = acc[i][1] + bvec.y;
        o.z = acc[i][2] + bvec.z;
        o.w = acc[i][3] + bvec.w;
        *(float4*)(out + (size_t)m * E_DIM + n0) = o;
    }
}

// ---------------------------------------------------------------------------
// Inputs (metadata order): query, key, value, in_proj_weight, in_proj_bias,
//                          out_proj_weight, out_proj_bias. Output: (S,B,E) f32.
// ---------------------------------------------------------------------------
extern "C" void kernel_launch(void* const* d_in, const int* in_sizes, int n_in,
                              void* d_out, int out_size)
{
    const float* query = (const float*)d_in[0];
    const float* key   = (const float*)d_in[1];
    const float* value = (const float*)d_in[2];
    const float* in_w  = (const float*)d_in[3];
    const float* in_b  = (const float*)d_in[4];
    const float* out_w = (const float*)d_in[5];
    const float* out_b = (const float*)d_in[6];
    float* out = (float*)d_out;

    dim3 projGrid(M_ROWS / 64, E_DIM / 64, 3);
    qkv_proj_kernel<<<projGrid, 256>>>(query, key, value, in_w, in_b);

    dim3 attnGrid(S_LEN / 64, B_SZ * H_NUM);
    attn_kernel<<<attnGrid, 128>>>();

    dim3 outGrid(M_ROWS / 64, E_DIM / 64);
    out_proj_kernel<<<outGrid, 256>>>(out_w, out_b, out);
}

// round 3
// speedup vs baseline: 1.0006x; 1.0006x over previous
#include <cuda_runtime.h>
#include <math.h>

#define S_LEN 2048
#define B_SZ  4
#define E_DIM 512
#define H_NUM 8
#define HD    64
#define M_ROWS (S_LEN * B_SZ)   // 8192

// Scratch (allocation-free rule: __device__ globals)
__device__ float g_qp[B_SZ * H_NUM * S_LEN * HD];   // (b*H+h, s, d), q pre-scaled by 1/8
__device__ float g_kp[B_SZ * H_NUM * S_LEN * HD];
__device__ float g_vp[B_SZ * H_NUM * S_LEN * HD];
__device__ float g_ctx[M_ROWS * E_DIM];             // (s*B+b, e) attention output

// ---------------------------------------------------------------------------
// QKV projection: C = X @ W^T + bias (optionally scaled), scattered to
// head-major layout. z=0: q (scale 1/8), z=1: k, z=2: v (weight rows 2E:3E).
// Tile: BM=BN=64, BK=16, 256 threads, 4x4 micro-tile per thread.
// ---------------------------------------------------------------------------
__global__ __launch_bounds__(256) void qkv_proj_kernel(
    const float* __restrict__ query, const float* __restrict__ key,
    const float* __restrict__ value, const float* __restrict__ W,
    const float* __restrict__ bias)
{
    const int z = blockIdx.z;
    const float* X  = (z == 0) ? query : (z == 1) ? key : value;
    const float* Wz = W    + ((z == 2) ? 2 * E_DIM * E_DIM : 0);
    const float* bz = bias + ((z == 2) ? 2 * E_DIM : 0);
    float* out      = (z == 0) ? g_qp : (z == 1) ? g_kp : g_vp;
    const float scale = (z == 0) ? 0.125f : 1.0f;

    __shared__ __align__(16) float Xs[16][64];
    __shared__ __align__(16) float Ws[16][64];

    const int mBase = blockIdx.x * 64;
    const int nBase = blockIdx.y * 64;
    const int t  = threadIdx.x;
    const int tx = t & 15;
    const int ty = t >> 4;

    float acc[4][4];
#pragma unroll
    for (int i = 0; i < 4; i++)
#pragma unroll
        for (int j = 0; j < 4; j++) acc[i][j] = 0.0f;

    const int lm = t >> 2;         // 0..63 row within tile
    const int lk = (t & 3) << 2;   // 0,4,8,12

    for (int k0 = 0; k0 < E_DIM; k0 += 16) {
        float4 xv = *(const float4*)(X  + (mBase + lm) * E_DIM + k0 + lk);
        float4 wv = *(const float4*)(Wz + (nBase + lm) * E_DIM + k0 + lk);
        Xs[lk + 0][lm] = xv.x; Xs[lk + 1][lm] = xv.y;
        Xs[lk + 2][lm] = xv.z; Xs[lk + 3][lm] = xv.w;
        Ws[lk + 0][lm] = wv.x; Ws[lk + 1][lm] = wv.y;
        Ws[lk + 2][lm] = wv.z; Ws[lk + 3][lm] = wv.w;
        __syncthreads();
#pragma unroll
        for (int kk = 0; kk < 16; kk++) {
            float4 a = *(const float4*)&Xs[kk][ty * 4];
            float4 b = *(const float4*)&Ws[kk][tx * 4];
            float av[4] = {a.x, a.y, a.z, a.w};
            float bv[4] = {b.x, b.y, b.z, b.w};
#pragma unroll
            for (int i = 0; i < 4; i++)
#pragma unroll
                for (int j = 0; j < 4; j++)
                    acc[i][j] = fmaf(av[i], bv[j], acc[i][j]);
        }
        __syncthreads();
    }

    // Epilogue: bias + scale, scatter to (b*H+h, s, d)
    const int n0 = nBase + tx * 4;
    const int h_ = n0 >> 6;        // head
    const int d0 = n0 & 63;        // dim within head (tile never crosses a head)
    const float4 bvec = *(const float4*)(bz + n0);
#pragma unroll
    for (int i = 0; i < 4; i++) {
        const int m  = mBase + ty * 4 + i;
        const int s_ = m >> 2;     // m = s*B + b, B=4
        const int b_ = m & 3;
        float4 o;
        o.x = (acc[i][0] + bvec.x) * scale;
        o.y = (acc[i][1] + bvec.y) * scale;
        o.z = (acc[i][2] + bvec.z) * scale;
        o.w = (acc[i][3] + bvec.w) * scale;
        *(float4*)(out + ((size_t)(b_ * H_NUM + h_) * S_LEN + s_) * HD + d0) = o;
    }
}

// ---------------------------------------------------------------------------
// Flash attention: one block per (head, 64-query tile). 128 threads:
// 2 threads per query row, each owning 32 of the 64 head dims.
// Online softmax, K/V streamed through smem in 64-key tiles.
// ---------------------------------------------------------------------------
__global__ __launch_bounds__(128) void attn_kernel()
{
    const int bh = blockIdx.y;     // b*H + h
    const int qt = blockIdx.x;
    const int t  = threadIdx.x;
    const int r    = t >> 1;       // query row within tile: 0..63
    const int half = t & 1;        // which 32-dim half

    const float* qrow = g_qp + ((size_t)bh * S_LEN + qt * 64 + r) * HD + half * 32;
    float q[32];
#pragma unroll
    for (int d = 0; d < 32; d++) q[d] = qrow[d];

    float o[32];
#pragma unroll
    for (int d = 0; d < 32; d++) o[d] = 0.0f;
    float mval = -1e30f;
    float lsum = 0.0f;

    __shared__ __align__(16) float Ks[64][64];
    __shared__ __align__(16) float Vs[64][64];

    const float* kbase = g_kp + (size_t)bh * S_LEN * HD;
    const float* vbase = g_vp + (size_t)bh * S_LEN * HD;

    for (int kt = 0; kt < S_LEN / 64; kt++) {
        __syncthreads();   // protect previous-iteration smem reads
        const float4* ksrc = (const float4*)(kbase + (size_t)kt * 64 * HD);
        const float4* vsrc = (const float4*)(vbase + (size_t)kt * 64 * HD);
        float4* kd = (float4*)&Ks[0][0];
        float4* vd = (float4*)&Vs[0][0];
#pragma unroll
        for (int i = 0; i < 8; i++) {
            kd[t + i * 128] = ksrc[t + i * 128];
            vd[t + i * 128] = vsrc[t + i * 128];
        }
        __syncthreads();

        float sreg[64];
#pragma unroll
        for (int j = 0; j < 64; j++) {
            float a = 0.0f;
            const float* kr = &Ks[j][half * 32];
#pragma unroll
            for (int d = 0; d < 32; d++) a = fmaf(q[d], kr[d], a);
            a += __shfl_xor_sync(0xffffffffu, a, 1);   // combine the two halves
            sreg[j] = a;
        }

        float mt = mval;
#pragma unroll
        for (int j = 0; j < 64; j++) mt = fmaxf(mt, sreg[j]);
        const float alpha = __expf(mval - mt);
        mval = mt;
        lsum *= alpha;
#pragma unroll
        for (int d = 0; d < 32; d++) o[d] *= alpha;

#pragma unroll
        for (int j = 0; j < 64; j++) {
            const float p = __expf(sreg[j] - mt);
            lsum += p;
            const float* vr = &Vs[j][half * 32];
#pragma unroll
            for (int d = 0; d < 32; d++) o[d] = fmaf(p, vr[d], o[d]);
        }
    }

    const float inv = 1.0f / lsum;
    const int b_ = bh >> 3;
    const int h_ = bh & 7;
    const int s_ = qt * 64 + r;
    float* dst = g_ctx + ((size_t)s_ * B_SZ + b_) * E_DIM + h_ * HD + half * 32;
#pragma unroll
    for (int d = 0; d < 32; d += 4) {
        float4 v4 = {o[d] * inv, o[d + 1] * inv, o[d + 2] * inv, o[d + 3] * inv};
        *(float4*)(dst + d) = v4;
    }
}

// ---------------------------------------------------------------------------
// Output projection: out = ctx @ Wo^T + bo, row-major (s*B+b, e) = (S,B,E)
// ---------------------------------------------------------------------------
__global__ __launch_bounds__(256) void out_proj_kernel(
    const float* __restrict__ Wo, const float* __restrict__ bo,
    float* __restrict__ out)
{
    __shared__ __align__(16) float Xs[16][64];
    __shared__ __align__(16) float Ws[16][64];

    const int mBase = blockIdx.x * 64;
    const int nBase = blockIdx.y * 64;
    const int t  = threadIdx.x;
    const int tx = t & 15;
    const int ty = t >> 4;

    float acc[4][4];
#pragma unroll
    for (int i = 0; i < 4; i++)
#pragma unroll
        for (int j = 0; j < 4; j++) acc[i][j] = 0.0f;

    const int lm = t >> 2;
    const int lk = (t & 3) << 2;

    for (int k0 = 0; k0 < E_DIM; k0 += 16) {
        float4 xv = *(const float4*)(g_ctx + (size_t)(mBase + lm) * E_DIM + k0 + lk);
        float4 wv = *(const float4*)(Wo    + (size_t)(nBase + lm) * E_DIM + k0 + lk);
        Xs[lk + 0][lm] = xv.x; Xs[lk + 1][lm] = xv.y;
        Xs[lk + 2][lm] = xv.z; Xs[lk + 3][lm] = xv.w;
        Ws[lk + 0][lm] = wv.x; Ws[lk + 1][lm] = wv.y;
        Ws[lk + 2][lm] = wv.z; Ws[lk + 3][lm] = wv.w;
        __syncthreads();
#pragma unroll
        for (int kk = 0; kk < 16; kk++) {
            float4 a = *(const float4*)&Xs[kk][ty * 4];
            float4 b = *(const float4*)&Ws[kk][tx * 4];
            float av[4] = {a.x, a.y, a.z, a.w};
            float bv[4] = {b.x, b.y, b.z, b.w};
#pragma unroll
            for (int i = 0; i < 4; i++)
#pragma unroll
                for (int j = 0; j < 4; j++)
                    acc[i][j] = fmaf(av[i], bv[j], acc[i][j]);
        }
        __syncthreads();
    }

    const int n0 = nBase + tx * 4;
    const float4 bvec = *(const float4*)(bo + n0);
#pragma unroll
    for (int i = 0; i < 4; i++) {
        const int m = mBase + ty * 4 + i;
        float4 o;
        o.x = acc[i][0] + bvec.x;
        o.y = acc[i][1] + bvec.y;
        o.z = acc[i][2] + bvec.z;
        o.w = acc[i][3] + bvec.w;
        *(float4*)(out + (size_t)m * E_DIM + n0) = o;
    }
}

// ---------------------------------------------------------------------------
// Inputs (metadata order): query, key, value, in_proj_weight, in_proj_bias,
//                          out_proj_weight, out_proj_bias. Output: (S,B,E) f32.
// ---------------------------------------------------------------------------
extern "C" void kernel_launch(void* const* d_in, const int* in_sizes, int n_in,
                              void* d_out, int out_size)
{
    const float* query = (const float*)d_in[0];
    const float* key   = (const float*)d_in[1];
    const float* value = (const float*)d_in[2];
    const float* in_w  = (const float*)d_in[3];
    const float* in_b  = (const float*)d_in[4];
    const float* out_w = (const float*)d_in[5];
    const float* out_b = (const float*)d_in[6];
    float* out = (float*)d_out;

    dim3 projGrid(M_ROWS / 64, E_DIM / 64, 3);
    qkv_proj_kernel<<<projGrid, 256>>>(query, key, value, in_w, in_b);

    dim3 attnGrid(S_LEN / 64, B_SZ * H_NUM);
    attn_kernel<<<attnGrid, 128>>>();

    dim3 outGrid(M_ROWS / 64, E_DIM / 64);
    out_proj_kernel<<<outGrid, 256>>>(out_w, out_b, out);
}

// round 4
// speedup vs baseline: 1.6497x; 1.6488x over previous
#include <cuda_runtime.h>
#include <math.h>

#define S_LEN 2048
#define B_SZ  4
#define E_DIM 512
#define H_NUM 8
#define HD    64
#define M_ROWS (S_LEN * B_SZ)   // 8192

// Scratch (allocation-free rule: __device__ globals)
__device__ float g_qp[B_SZ * H_NUM * S_LEN * HD];   // (b*H+h, s, d), q pre-scaled by 1/8
__device__ float g_kp[B_SZ * H_NUM * S_LEN * HD];
__device__ float g_vp[B_SZ * H_NUM * S_LEN * HD];
__device__ float g_ctx[M_ROWS * E_DIM];             // (s*B+b, e) attention output

// ---------------------------------------------------------------------------
// QKV projection: C = X @ W^T + bias (optionally scaled), scattered to
// head-major layout. z=0: q (scale 1/8), z=1: k, z=2: v (weight rows 2E:3E).
// Tile: BM=BN=64, BK=16, 256 threads, 4x4 micro-tile, register prefetch.
// ---------------------------------------------------------------------------
__global__ __launch_bounds__(256) void qkv_proj_kernel(
    const float* __restrict__ query, const float* __restrict__ key,
    const float* __restrict__ value, const float* __restrict__ W,
    const float* __restrict__ bias)
{
    const int z = blockIdx.z;
    const float* X  = (z == 0) ? query : (z == 1) ? key : value;
    const float* Wz = W    + ((z == 2) ? 2 * E_DIM * E_DIM : 0);
    const float* bz = bias + ((z == 2) ? 2 * E_DIM : 0);
    float* out      = (z == 0) ? g_qp : (z == 1) ? g_kp : g_vp;
    const float scale = (z == 0) ? 0.125f : 1.0f;

    __shared__ __align__(16) float Xs[16][64];
    __shared__ __align__(16) float Ws[16][64];

    const int mBase = blockIdx.x * 64;
    const int nBase = blockIdx.y * 64;
    const int t  = threadIdx.x;
    const int tx = t & 15;
    const int ty = t >> 4;

    float acc[4][4];
#pragma unroll
    for (int i = 0; i < 4; i++)
#pragma unroll
        for (int j = 0; j < 4; j++) acc[i][j] = 0.0f;

    const int lm = t >> 2;         // 0..63 row within tile
    const int lk = (t & 3) << 2;   // 0,4,8,12

    // prefetch first chunk
    float4 xv = *(const float4*)(X  + (mBase + lm) * E_DIM + lk);
    float4 wv = *(const float4*)(Wz + (nBase + lm) * E_DIM + lk);

    for (int k0 = 0; k0 < E_DIM; k0 += 16) {
        Xs[lk + 0][lm] = xv.x; Xs[lk + 1][lm] = xv.y;
        Xs[lk + 2][lm] = xv.z; Xs[lk + 3][lm] = xv.w;
        Ws[lk + 0][lm] = wv.x; Ws[lk + 1][lm] = wv.y;
        Ws[lk + 2][lm] = wv.z; Ws[lk + 3][lm] = wv.w;
        __syncthreads();
        if (k0 + 16 < E_DIM) {
            xv = *(const float4*)(X  + (mBase + lm) * E_DIM + k0 + 16 + lk);
            wv = *(const float4*)(Wz + (nBase + lm) * E_DIM + k0 + 16 + lk);
        }
#pragma unroll
        for (int kk = 0; kk < 16; kk++) {
            float4 a = *(const float4*)&Xs[kk][ty * 4];
            float4 b = *(const float4*)&Ws[kk][tx * 4];
            float av[4] = {a.x, a.y, a.z, a.w};
            float bv[4] = {b.x, b.y, b.z, b.w};
#pragma unroll
            for (int i = 0; i < 4; i++)
#pragma unroll
                for (int j = 0; j < 4; j++)
                    acc[i][j] = fmaf(av[i], bv[j], acc[i][j]);
        }
        __syncthreads();
    }

    // Epilogue: bias + scale, scatter to (b*H+h, s, d)
    const int n0 = nBase + tx * 4;
    const int h_ = n0 >> 6;        // head
    const int d0 = n0 & 63;        // dim within head (tile never crosses a head)
    const float4 bvec = *(const float4*)(bz + n0);
#pragma unroll
    for (int i = 0; i < 4; i++) {
        const int m  = mBase + ty * 4 + i;
        const int s_ = m >> 2;     // m = s*B + b, B=4
        const int b_ = m & 3;
        float4 o;
        o.x = (acc[i][0] + bvec.x) * scale;
        o.y = (acc[i][1] + bvec.y) * scale;
        o.z = (acc[i][2] + bvec.z) * scale;
        o.w = (acc[i][3] + bvec.w) * scale;
        *(float4*)(out + ((size_t)(b_ * H_NUM + h_) * S_LEN + s_) * HD + d0) = o;
    }
}

// ---------------------------------------------------------------------------
// Flash attention v2 (GEMM-structured): one block per (head, 64-query tile).
// 256 threads. Both S = Q@K^T and O += P@V use 4x4 per-thread micro-tiles.
// P staged through smem, aliasing the K buffer (total static smem = 48 KB).
// Smem layouts: Qs[d][r], KP = K as [d][c] then P as [r][k], Vs[k][d].
// ---------------------------------------------------------------------------
__global__ __launch_bounds__(256) void attn_kernel_v2()
{
    const int bh = blockIdx.y;     // b*H + h
    const int qt = blockIdx.x;
    const int t  = threadIdx.x;
    const int tx = t & 15;         // column group (keys in QK, head-dims in PV)
    const int ty = t >> 4;         // row group (queries)
    const int r0 = ty * 4;
    const int c0 = tx * 4;

    __shared__ __align__(16) float Qs[64 * 64];  // [d][r]
    __shared__ __align__(16) float KP[64 * 64];  // K: [d][c] -> later P: [r][k]
    __shared__ __align__(16) float Vs[64 * 64];  // [k][d]

    const float* qbase = g_qp + ((size_t)bh * S_LEN + qt * 64) * HD;
    const float* kbase = g_kp + (size_t)bh * S_LEN * HD;
    const float* vbase = g_vp + (size_t)bh * S_LEN * HD;

    // Load Q tile transposed: thread -> one row, 16 dims
    {
        const int row = t & 63;
        const int d0  = (t >> 6) * 16;
        const float* qr = qbase + row * HD + d0;
#pragma unroll
        for (int q = 0; q < 4; q++) {
            float4 v = *(const float4*)(qr + q * 4);
            Qs[(d0 + q * 4 + 0) * 64 + row] = v.x;
            Qs[(d0 + q * 4 + 1) * 64 + row] = v.y;
            Qs[(d0 + q * 4 + 2) * 64 + row] = v.z;
            Qs[(d0 + q * 4 + 3) * 64 + row] = v.w;
        }
    }

    float O[4][4];
    float m_s[4], l_s[4];
#pragma unroll
    for (int i = 0; i < 4; i++) {
        m_s[i] = -1e30f;
        l_s[i] = 0.0f;
#pragma unroll
        for (int j = 0; j < 4; j++) O[i][j] = 0.0f;
    }

    for (int kt2 = 0; kt2 < S_LEN / 64; kt2++) {
        __syncthreads();   // prior PV done: safe to overwrite KP (P) and Vs

        // K tile transposed into KP[d][key]
        {
            const int key = t & 63;
            const int d0  = (t >> 6) * 16;
            const float* kr = kbase + ((size_t)kt2 * 64 + key) * HD + d0;
#pragma unroll
            for (int q = 0; q < 4; q++) {
                float4 v = *(const float4*)(kr + q * 4);
                KP[(d0 + q * 4 + 0) * 64 + key] = v.x;
                KP[(d0 + q * 4 + 1) * 64 + key] = v.y;
                KP[(d0 + q * 4 + 2) * 64 + key] = v.z;
                KP[(d0 + q * 4 + 3) * 64 + key] = v.w;
            }
            // V tile linear copy (row-major [key][d])
            const float4* vsrc = (const float4*)(vbase + (size_t)kt2 * 64 * HD);
            float4* vd = (float4*)Vs;
#pragma unroll
            for (int i = 0; i < 4; i++) vd[t + i * 256] = vsrc[t + i * 256];
        }
        __syncthreads();

        // --- S = Q @ K^T (4x4 micro-tile) ---
        float s[4][4];
#pragma unroll
        for (int i = 0; i < 4; i++)
#pragma unroll
            for (int j = 0; j < 4; j++) s[i][j] = 0.0f;

#pragma unroll 8
        for (int d = 0; d < 64; d++) {
            float4 a = *(const float4*)&Qs[d * 64 + r0];
            float4 b = *(const float4*)&KP[d * 64 + c0];
            float av[4] = {a.x, a.y, a.z, a.w};
            float bv[4] = {b.x, b.y, b.z, b.w};
#pragma unroll
            for (int i = 0; i < 4; i++)
#pragma unroll
                for (int j = 0; j < 4; j++)
                    s[i][j] = fmaf(av[i], bv[j], s[i][j]);
        }

        // --- online softmax: row stats via 16-lane shfl reductions ---
        float alpha[4];
#pragma unroll
        for (int i = 0; i < 4; i++) {
            float mx = fmaxf(fmaxf(s[i][0], s[i][1]), fmaxf(s[i][2], s[i][3]));
#pragma unroll
            for (int o = 1; o < 16; o <<= 1)
                mx = fmaxf(mx, __shfl_xor_sync(0xffffffffu, mx, o));
            const float mnew = fmaxf(m_s[i], mx);
            alpha[i] = __expf(m_s[i] - mnew);
            m_s[i] = mnew;
            float ps = 0.0f;
#pragma unroll
            for (int j = 0; j < 4; j++) {
                s[i][j] = __expf(s[i][j] - mnew);   // s becomes p
                ps += s[i][j];
            }
#pragma unroll
            for (int o = 1; o < 16; o <<= 1)
                ps += __shfl_xor_sync(0xffffffffu, ps, o);
            l_s[i] = l_s[i] * alpha[i] + ps;
        }

        __syncthreads();   // everyone done reading K from KP

        // store P row-major into KP: P[r][k]
#pragma unroll
        for (int i = 0; i < 4; i++) {
            float4 p4 = {s[i][0], s[i][1], s[i][2], s[i][3]};
            *(float4*)&KP[(r0 + i) * 64 + c0] = p4;
        }
        __syncthreads();

        // --- O = O*alpha + P @ V (4x4 micro-tile, k unrolled by 4) ---
#pragma unroll
        for (int i = 0; i < 4; i++)
#pragma unroll
            for (int j = 0; j < 4; j++) O[i][j] *= alpha[i];

#pragma unroll 4
        for (int k0 = 0; k0 < 64; k0 += 4) {
            float4 a4[4], b4[4];
#pragma unroll
            for (int i = 0; i < 4; i++)
                a4[i] = *(const float4*)&KP[(r0 + i) * 64 + k0];
#pragma unroll
            for (int kk = 0; kk < 4; kk++)
                b4[kk] = *(const float4*)&Vs[(k0 + kk) * 64 + c0];
#pragma unroll
            for (int i = 0; i < 4; i++) {
                float av[4] = {a4[i].x, a4[i].y, a4[i].z, a4[i].w};
#pragma unroll
                for (int kk = 0; kk < 4; kk++) {
                    float bv[4] = {b4[kk].x, b4[kk].y, b4[kk].z, b4[kk].w};
#pragma unroll
                    for (int j = 0; j < 4; j++)
                        O[i][j] = fmaf(av[kk], bv[j], O[i][j]);
                }
            }
        }
    }

    // epilogue: normalize and scatter to g_ctx (s*B+b, h*64+d)
    const int b_ = bh >> 3;
    const int h_ = bh & 7;
#pragma unroll
    for (int i = 0; i < 4; i++) {
        const float inv = 1.0f / l_s[i];
        const int s_ = qt * 64 + r0 + i;
        float4 o4 = {O[i][0] * inv, O[i][1] * inv, O[i][2] * inv, O[i][3] * inv};
        *(float4*)(g_ctx + ((size_t)s_ * B_SZ + b_) * E_DIM + h_ * HD + c0) = o4;
    }
}

// ---------------------------------------------------------------------------
// Output projection: out = ctx @ Wo^T + bo, row-major (s*B+b, e) = (S,B,E)
// ---------------------------------------------------------------------------
__global__ __launch_bounds__(256) void out_proj_kernel(
    const float* __restrict__ Wo, const float* __restrict__ bo,
    float* __restrict__ out)
{
    __shared__ __align__(16) float Xs[16][64];
    __shared__ __align__(16) float Ws[16][64];

    const int mBase = blockIdx.x * 64;
    const int nBase = blockIdx.y * 64;
    const int t  = threadIdx.x;
    const int tx = t & 15;
    const int ty = t >> 4;

    float acc[4][4];
#pragma unroll
    for (int i = 0; i < 4; i++)
#pragma unroll
        for (int j = 0; j < 4; j++) acc[i][j] = 0.0f;

    const int lm = t >> 2;
    const int lk = (t & 3) << 2;

    float4 xv = *(const float4*)(g_ctx + (size_t)(mBase + lm) * E_DIM + lk);
    float4 wv = *(const float4*)(Wo    + (size_t)(nBase + lm) * E_DIM + lk);

    for (int k0 = 0; k0 < E_DIM; k0 += 16) {
        Xs[lk + 0][lm] = xv.x; Xs[lk + 1][lm] = xv.y;
        Xs[lk + 2][lm] = xv.z; Xs[lk + 3][lm] = xv.w;
        Ws[lk + 0][lm] = wv.x; Ws[lk + 1][lm] = wv.y;
        Ws[lk + 2][lm] = wv.z; Ws[lk + 3][lm] = wv.w;
        __syncthreads();
        if (k0 + 16 < E_DIM) {
            xv = *(const float4*)(g_ctx + (size_t)(mBase + lm) * E_DIM + k0 + 16 + lk);
            wv = *(const float4*)(Wo    + (size_t)(nBase + lm) * E_DIM + k0 + 16 + lk);
        }
#pragma unroll
        for (int kk = 0; kk < 16; kk++) {
            float4 a = *(const float4*)&Xs[kk][ty * 4];
            float4 b = *(const float4*)&Ws[kk][tx * 4];
            float av[4] = {a.x, a.y, a.z, a.w};
            float bv[4] = {b.x, b.y, b.z, b.w};
#pragma unroll
            for (int i = 0; i < 4; i++)
#pragma unroll
                for (int j = 0; j < 4; j++)
                    acc[i][j] = fmaf(av[i], bv[j], acc[i][j]);
        }
        __syncthreads();
    }

    const int n0 = nBase + tx * 4;
    const float4 bvec = *(const float4*)(bo + n0);
#pragma unroll
    for (int i = 0; i < 4; i++) {
        const int m = mBase + ty * 4 + i;
        float4 o;
        o.x = acc[i][0] + bvec.x;
        o.y = acc[i][1] + bvec.y;
        o.z = acc[i][2] + bvec.z;
        o.w = acc[i][3] + bvec.w;
        *(float4*)(out + (size_t)m * E_DIM + n0) = o;
    }
}

// ---------------------------------------------------------------------------
// Inputs (metadata order): query, key, value, in_proj_weight, in_proj_bias,
//                          out_proj_weight, out_proj_bias. Output: (S,B,E) f32.
// ---------------------------------------------------------------------------
extern "C" void kernel_launch(void* const* d_in, const int* in_sizes, int n_in,
                              void* d_out, int out_size)
{
    const float* query = (const float*)d_in[0];
    const float* key   = (const float*)d_in[1];
    const float* value = (const float*)d_in[2];
    const float* in_w  = (const float*)d_in[3];
    const float* in_b  = (const float*)d_in[4];
    const float* out_w = (const float*)d_in[5];
    const float* out_b = (const float*)d_in[6];
    float* out = (float*)d_out;

    dim3 projGrid(M_ROWS / 64, E_DIM / 64, 3);
    qkv_proj_kernel<<<projGrid, 256>>>(query, key, value, in_w, in_b);

    dim3 attnGrid(S_LEN / 64, B_SZ * H_NUM);
    attn_kernel_v2<<<attnGrid, 256>>>();

    dim3 outGrid(M_ROWS / 64, E_DIM / 64);
    out_proj_kernel<<<outGrid, 256>>>(out_w, out_b, out);
}

// round 5
// speedup vs baseline: 1.6515x; 1.0011x over previous
#include <cuda_runtime.h>
#include <math.h>

#define S_LEN 2048
#define B_SZ  4
#define E_DIM 512
#define H_NUM 8
#define HD    64
#define M_ROWS (S_LEN * B_SZ)   // 8192

// Scratch (allocation-free rule: __device__ globals)
__device__ float g_qp[B_SZ * H_NUM * S_LEN * HD];   // (b*H+h, s, d), q pre-scaled by 1/8
__device__ float g_kp[B_SZ * H_NUM * S_LEN * HD];
__device__ float g_vp[B_SZ * H_NUM * S_LEN * HD];
__device__ float g_ctx[M_ROWS * E_DIM];             // (s*B+b, e) attention output

// ---------------------------------------------------------------------------
// QKV projection: C = X @ W^T + bias (optionally scaled), scattered to
// head-major layout. z=0: q (scale 1/8), z=1: k, z=2: v (weight rows 2E:3E).
// Tile: BM=BN=64, BK=16, 256 threads, 4x4 micro-tile, register prefetch.
// ---------------------------------------------------------------------------
__global__ __launch_bounds__(256) void qkv_proj_kernel(
    const float* __restrict__ query, const float* __restrict__ key,
    const float* __restrict__ value, const float* __restrict__ W,
    const float* __restrict__ bias)
{
    const int z = blockIdx.z;
    const float* X  = (z == 0) ? query : (z == 1) ? key : value;
    const float* Wz = W    + ((z == 2) ? 2 * E_DIM * E_DIM : 0);
    const float* bz = bias + ((z == 2) ? 2 * E_DIM : 0);
    float* out      = (z == 0) ? g_qp : (z == 1) ? g_kp : g_vp;
    const float scale = (z == 0) ? 0.125f : 1.0f;

    __shared__ __align__(16) float Xs[16][64];
    __shared__ __align__(16) float Ws[16][64];

    const int mBase = blockIdx.x * 64;
    const int nBase = blockIdx.y * 64;
    const int t  = threadIdx.x;
    const int tx = t & 15;
    const int ty = t >> 4;

    float acc[4][4];
#pragma unroll
    for (int i = 0; i < 4; i++)
#pragma unroll
        for (int j = 0; j < 4; j++) acc[i][j] = 0.0f;

    const int lm = t >> 2;         // 0..63 row within tile
    const int lk = (t & 3) << 2;   // 0,4,8,12

    // prefetch first chunk
    float4 xv = *(const float4*)(X  + (mBase + lm) * E_DIM + lk);
    float4 wv = *(const float4*)(Wz + (nBase + lm) * E_DIM + lk);

    for (int k0 = 0; k0 < E_DIM; k0 += 16) {
        Xs[lk + 0][lm] = xv.x; Xs[lk + 1][lm] = xv.y;
        Xs[lk + 2][lm] = xv.z; Xs[lk + 3][lm] = xv.w;
        Ws[lk + 0][lm] = wv.x; Ws[lk + 1][lm] = wv.y;
        Ws[lk + 2][lm] = wv.z; Ws[lk + 3][lm] = wv.w;
        __syncthreads();
        if (k0 + 16 < E_DIM) {
            xv = *(const float4*)(X  + (mBase + lm) * E_DIM + k0 + 16 + lk);
            wv = *(const float4*)(Wz + (nBase + lm) * E_DIM + k0 + 16 + lk);
        }
#pragma unroll
        for (int kk = 0; kk < 16; kk++) {
            float4 a = *(const float4*)&Xs[kk][ty * 4];
            float4 b = *(const float4*)&Ws[kk][tx * 4];
            float av[4] = {a.x, a.y, a.z, a.w};
            float bv[4] = {b.x, b.y, b.z, b.w};
#pragma unroll
            for (int i = 0; i < 4; i++)
#pragma unroll
                for (int j = 0; j < 4; j++)
                    acc[i][j] = fmaf(av[i], bv[j], acc[i][j]);
        }
        __syncthreads();
    }

    // Epilogue: bias + scale, scatter to (b*H+h, s, d)
    const int n0 = nBase + tx * 4;
    const int h_ = n0 >> 6;        // head
    const int d0 = n0 & 63;        // dim within head (tile never crosses a head)
    const float4 bvec = *(const float4*)(bz + n0);
#pragma unroll
    for (int i = 0; i < 4; i++) {
        const int m  = mBase + ty * 4 + i;
        const int s_ = m >> 2;     // m = s*B + b, B=4
        const int b_ = m & 3;
        float4 o;
        o.x = (acc[i][0] + bvec.x) * scale;
        o.y = (acc[i][1] + bvec.y) * scale;
        o.z = (acc[i][2] + bvec.z) * scale;
        o.w = (acc[i][3] + bvec.w) * scale;
        *(float4*)(out + ((size_t)(b_ * H_NUM + h_) * S_LEN + s_) * HD + d0) = o;
    }
}

// ---------------------------------------------------------------------------
// Flash attention v2 (GEMM-structured): one block per (head, 64-query tile).
// 256 threads. Both S = Q@K^T and O += P@V use 4x4 per-thread micro-tiles.
// P staged through smem, aliasing the K buffer (total static smem = 48 KB).
// Smem layouts: Qs[d][r], KP = K as [d][c] then P as [r][k], Vs[k][d].
// ---------------------------------------------------------------------------
__global__ __launch_bounds__(256) void attn_kernel_v2()
{
    const int bh = blockIdx.y;     // b*H + h
    const int qt = blockIdx.x;
    const int t  = threadIdx.x;
    const int tx = t & 15;         // column group (keys in QK, head-dims in PV)
    const int ty = t >> 4;         // row group (queries)
    const int r0 = ty * 4;
    const int c0 = tx * 4;

    __shared__ __align__(16) float Qs[64 * 64];  // [d][r]
    __shared__ __align__(16) float KP[64 * 64];  // K: [d][c] -> later P: [r][k]
    __shared__ __align__(16) float Vs[64 * 64];  // [k][d]

    const float* qbase = g_qp + ((size_t)bh * S_LEN + qt * 64) * HD;
    const float* kbase = g_kp + (size_t)bh * S_LEN * HD;
    const float* vbase = g_vp + (size_t)bh * S_LEN * HD;

    // Load Q tile transposed: thread -> one row, 16 dims
    {
        const int row = t & 63;
        const int d0  = (t >> 6) * 16;
        const float* qr = qbase + row * HD + d0;
#pragma unroll
        for (int q = 0; q < 4; q++) {
            float4 v = *(const float4*)(qr + q * 4);
            Qs[(d0 + q * 4 + 0) * 64 + row] = v.x;
            Qs[(d0 + q * 4 + 1) * 64 + row] = v.y;
            Qs[(d0 + q * 4 + 2) * 64 + row] = v.z;
            Qs[(d0 + q * 4 + 3) * 64 + row] = v.w;
        }
    }

    float O[4][4];
    float m_s[4], l_s[4];
#pragma unroll
    for (int i = 0; i < 4; i++) {
        m_s[i] = -1e30f;
        l_s[i] = 0.0f;
#pragma unroll
        for (int j = 0; j < 4; j++) O[i][j] = 0.0f;
    }

    for (int kt2 = 0; kt2 < S_LEN / 64; kt2++) {
        __syncthreads();   // prior PV done: safe to overwrite KP (P) and Vs

        // K tile transposed into KP[d][key]
        {
            const int key = t & 63;
            const int d0  = (t >> 6) * 16;
            const float* kr = kbase + ((size_t)kt2 * 64 + key) * HD + d0;
#pragma unroll
            for (int q = 0; q < 4; q++) {
                float4 v = *(const float4*)(kr + q * 4);
                KP[(d0 + q * 4 + 0) * 64 + key] = v.x;
                KP[(d0 + q * 4 + 1) * 64 + key] = v.y;
                KP[(d0 + q * 4 + 2) * 64 + key] = v.z;
                KP[(d0 + q * 4 + 3) * 64 + key] = v.w;
            }
            // V tile linear copy (row-major [key][d])
            const float4* vsrc = (const float4*)(vbase + (size_t)kt2 * 64 * HD);
            float4* vd = (float4*)Vs;
#pragma unroll
            for (int i = 0; i < 4; i++) vd[t + i * 256] = vsrc[t + i * 256];
        }
        __syncthreads();

        // --- S = Q @ K^T (4x4 micro-tile) ---
        float s[4][4];
#pragma unroll
        for (int i = 0; i < 4; i++)
#pragma unroll
            for (int j = 0; j < 4; j++) s[i][j] = 0.0f;

#pragma unroll 8
        for (int d = 0; d < 64; d++) {
            float4 a = *(const float4*)&Qs[d * 64 + r0];
            float4 b = *(const float4*)&KP[d * 64 + c0];
            float av[4] = {a.x, a.y, a.z, a.w};
            float bv[4] = {b.x, b.y, b.z, b.w};
#pragma unroll
            for (int i = 0; i < 4; i++)
#pragma unroll
                for (int j = 0; j < 4; j++)
                    s[i][j] = fmaf(av[i], bv[j], s[i][j]);
        }

        // --- online softmax: row stats via 16-lane shfl reductions ---
        float alpha[4];
#pragma unroll
        for (int i = 0; i < 4; i++) {
            float mx = fmaxf(fmaxf(s[i][0], s[i][1]), fmaxf(s[i][2], s[i][3]));
#pragma unroll
            for (int o = 1; o < 16; o <<= 1)
                mx = fmaxf(mx, __shfl_xor_sync(0xffffffffu, mx, o));
            const float mnew = fmaxf(m_s[i], mx);
            alpha[i] = __expf(m_s[i] - mnew);
            m_s[i] = mnew;
            float ps = 0.0f;
#pragma unroll
            for (int j = 0; j < 4; j++) {
                s[i][j] = __expf(s[i][j] - mnew);   // s becomes p
                ps += s[i][j];
            }
#pragma unroll
            for (int o = 1; o < 16; o <<= 1)
                ps += __shfl_xor_sync(0xffffffffu, ps, o);
            l_s[i] = l_s[i] * alpha[i] + ps;
        }

        __syncthreads();   // everyone done reading K from KP

        // store P row-major into KP: P[r][k]
#pragma unroll
        for (int i = 0; i < 4; i++) {
            float4 p4 = {s[i][0], s[i][1], s[i][2], s[i][3]};
            *(float4*)&KP[(r0 + i) * 64 + c0] = p4;
        }
        __syncthreads();

        // --- O = O*alpha + P @ V (4x4 micro-tile, k unrolled by 4) ---
#pragma unroll
        for (int i = 0; i < 4; i++)
#pragma unroll
            for (int j = 0; j < 4; j++) O[i][j] *= alpha[i];

#pragma unroll 4
        for (int k0 = 0; k0 < 64; k0 += 4) {
            float4 a4[4], b4[4];
#pragma unroll
            for (int i = 0; i < 4; i++)
                a4[i] = *(const float4*)&KP[(r0 + i) * 64 + k0];
#pragma unroll
            for (int kk = 0; kk < 4; kk++)
                b4[kk] = *(const float4*)&Vs[(k0 + kk) * 64 + c0];
#pragma unroll
            for (int i = 0; i < 4; i++) {
                float av[4] = {a4[i].x, a4[i].y, a4[i].z, a4[i].w};
#pragma unroll
                for (int kk = 0; kk < 4; kk++) {
                    float bv[4] = {b4[kk].x, b4[kk].y, b4[kk].z, b4[kk].w};
#pragma unroll
                    for (int j = 0; j < 4; j++)
                        O[i][j] = fmaf(av[kk], bv[j], O[i][j]);
                }
            }
        }
    }

    // epilogue: normalize and scatter to g_ctx (s*B+b, h*64+d)
    const int b_ = bh >> 3;
    const int h_ = bh & 7;
#pragma unroll
    for (int i = 0; i < 4; i++) {
        const float inv = 1.0f / l_s[i];
        const int s_ = qt * 64 + r0 + i;
        float4 o4 = {O[i][0] * inv, O[i][1] * inv, O[i][2] * inv, O[i][3] * inv};
        *(float4*)(g_ctx + ((size_t)s_ * B_SZ + b_) * E_DIM + h_ * HD + c0) = o4;
    }
}

// ---------------------------------------------------------------------------
// Output projection: out = ctx @ Wo^T + bo, row-major (s*B+b, e) = (S,B,E)
// ---------------------------------------------------------------------------
__global__ __launch_bounds__(256) void out_proj_kernel(
    const float* __restrict__ Wo, const float* __restrict__ bo,
    float* __restrict__ out)
{
    __shared__ __align__(16) float Xs[16][64];
    __shared__ __align__(16) float Ws[16][64];

    const int mBase = blockIdx.x * 64;
    const int nBase = blockIdx.y * 64;
    const int t  = threadIdx.x;
    const int tx = t & 15;
    const int ty = t >> 4;

    float acc[4][4];
#pragma unroll
    for (int i = 0; i < 4; i++)
#pragma unroll
        for (int j = 0; j < 4; j++) acc[i][j] = 0.0f;

    const int lm = t >> 2;
    const int lk = (t & 3) << 2;

    float4 xv = *(const float4*)(g_ctx + (size_t)(mBase + lm) * E_DIM + lk);
    float4 wv = *(const float4*)(Wo    + (size_t)(nBase + lm) * E_DIM + lk);

    for (int k0 = 0; k0 < E_DIM; k0 += 16) {
        Xs[lk + 0][lm] = xv.x; Xs[lk + 1][lm] = xv.y;
        Xs[lk + 2][lm] = xv.z; Xs[lk + 3][lm] = xv.w;
        Ws[lk + 0][lm] = wv.x; Ws[lk + 1][lm] = wv.y;
        Ws[lk + 2][lm] = wv.z; Ws[lk + 3][lm] = wv.w;
        __syncthreads();
        if (k0 + 16 < E_DIM) {
            xv = *(const float4*)(g_ctx + (size_t)(mBase + lm) * E_DIM + k0 + 16 + lk);
            wv = *(const float4*)(Wo    + (size_t)(nBase + lm) * E_DIM + k0 + 16 + lk);
        }
#pragma unroll
        for (int kk = 0; kk < 16; kk++) {
            float4 a = *(const float4*)&Xs[kk][ty * 4];
            float4 b = *(const float4*)&Ws[kk][tx * 4];
            float av[4] = {a.x, a.y, a.z, a.w};
            float bv[4] = {b.x, b.y, b.z, b.w};
#pragma unroll
            for (int i = 0; i < 4; i++)
#pragma unroll
                for (int j = 0; j < 4; j++)
                    acc[i][j] = fmaf(av[i], bv[j], acc[i][j]);
        }
        __syncthreads();
    }

    const int n0 = nBase + tx * 4;
    const float4 bvec = *(const float4*)(bo + n0);
#pragma unroll
    for (int i = 0; i < 4; i++) {
        const int m = mBase + ty * 4 + i;
        float4 o;
        o.x = acc[i][0] + bvec.x;
        o.y = acc[i][1] + bvec.y;
        o.z = acc[i][2] + bvec.z;
        o.w = acc[i][3] + bvec.w;
        *(float4*)(out + (size_t)m * E_DIM + n0) = o;
    }
}

// ---------------------------------------------------------------------------
// Inputs (metadata order): query, key, value, in_proj_weight, in_proj_bias,
//                          out_proj_weight, out_proj_bias. Output: (S,B,E) f32.
// ---------------------------------------------------------------------------
extern "C" void kernel_launch(void* const* d_in, const int* in_sizes, int n_in,
                              void* d_out, int out_size)
{
    const float* query = (const float*)d_in[0];
    const float* key   = (const float*)d_in[1];
    const float* value = (const float*)d_in[2];
    const float* in_w  = (const float*)d_in[3];
    const float* in_b  = (const float*)d_in[4];
    const float* out_w = (const float*)d_in[5];
    const float* out_b = (const float*)d_in[6];
    float* out = (float*)d_out;

    dim3 projGrid(M_ROWS / 64, E_DIM / 64, 3);
    qkv_proj_kernel<<<projGrid, 256>>>(query, key, value, in_w, in_b);

    dim3 attnGrid(S_LEN / 64, B_SZ * H_NUM);
    attn_kernel_v2<<<attnGrid, 256>>>();

    dim3 outGrid(M_ROWS / 64, E_DIM / 64);
    out_proj_kernel<<<outGrid, 256>>>(out_w, out_b, out);
}

// round 8
// speedup vs baseline: 2.6592x; 1.6102x over previous
#include <cuda_runtime.h>
#include <cuda_bf16.h>
#include <cstdint>
#include <math.h>

#define S_LEN 2048
#define B_SZ  4
#define E_DIM 512
#define H_NUM 8
#define HD    64
#define M_ROWS (S_LEN * B_SZ)
#define NBH   (B_SZ * H_NUM)
#define NT64  (S_LEN / 64)     // 32 key tiles of 64

// ---------------- scratch ----------------------------------------------------
__device__ __align__(16) __nv_bfloat16 g_qh[NBH * S_LEN * HD];  // [bh][s][d]
__device__ __align__(16) __nv_bfloat16 g_ql[NBH * S_LEN * HD];
__device__ __align__(16) __nv_bfloat16 g_kh[NBH * S_LEN * HD];  // [bh][s][d]
__device__ __align__(16) __nv_bfloat16 g_kl[NBH * S_LEN * HD];
__device__ __align__(16) __nv_bfloat16 g_vh[NBH * S_LEN * HD];  // [bh][d][s]
__device__ __align__(16) __nv_bfloat16 g_vl[NBH * S_LEN * HD];
__device__ float g_ctx[M_ROWS * E_DIM];

// ---------------- helpers -----------------------------------------------------
__device__ __forceinline__ uint32_t smem_u32(const void* p) {
    uint32_t a;
    asm("{ .reg .u64 t; cvta.to.shared.u64 t, %1; cvt.u32.u64 %0, t; }" : "=r"(a) : "l"(p));
    return a;
}
__device__ __forceinline__ float ex2(float x) {
    float y; asm("ex2.approx.f32 %0, %1;" : "=f"(y) : "f"(x)); return y;
}
__device__ __forceinline__ void ldmx4(uint32_t* r, uint32_t addr) {
    asm volatile("ldmatrix.sync.aligned.m8n8.x4.shared.b16 {%0,%1,%2,%3}, [%4];"
                 : "=r"(r[0]), "=r"(r[1]), "=r"(r[2]), "=r"(r[3]) : "r"(addr));
}
__device__ __forceinline__ void mma16816(float* d, const uint32_t* a, const uint32_t* b) {
    asm volatile("mma.sync.aligned.m16n8k16.row.col.f32.bf16.bf16.f32 "
                 "{%0,%1,%2,%3}, {%4,%5,%6,%7}, {%8,%9}, {%0,%1,%2,%3};"
                 : "+f"(d[0]), "+f"(d[1]), "+f"(d[2]), "+f"(d[3])
                 : "r"(a[0]), "r"(a[1]), "r"(a[2]), "r"(a[3]), "r"(b[0]), "r"(b[1]));
}
__device__ __forceinline__ void split_pack(float v0, float v1, uint32_t& hp, uint32_t& lp) {
    __nv_bfloat16 h0 = __float2bfloat16(v0), h1 = __float2bfloat16(v1);
    float l0 = v0 - __bfloat162float(h0), l1 = v1 - __bfloat162float(h1);
    hp = ((uint32_t)__bfloat16_as_ushort(h1) << 16) | __bfloat16_as_ushort(h0);
    asm("cvt.rn.bf16x2.f32 %0, %1, %2;" : "=r"(lp) : "f"(l1), "f"(l0));
}
__device__ __forceinline__ void bf16_split(float v, uint16_t& h, uint16_t& l) {
    __nv_bfloat16 hb = __float2bfloat16(v);
    __nv_bfloat16 lb = __float2bfloat16(v - __bfloat162float(hb));
    h = __bfloat16_as_ushort(hb); l = __bfloat16_as_ushort(lb);
}
#define SWZ(x) ((x) ^ (((x) >> 3) & 0x70))

// smem layout (dynamic, bytes). Q: 128x64 hi+lo. K/V: 64x64 hi+lo, 2 buffers.
#define SQ_H 0
#define SQ_L 16384
#define SK   32768      // buf b: KH = SK + b*16384, KL = +8192
#define SV   65536      // buf b: VH = SV + b*16384, VL = +8192
#define SMEM_ATTN 98304

// ---------------------------------------------------------------------------
// QKV projection -> bf16 hi/lo. z=0: q (*0.125*log2e), z=1: k, z=2: v (rows
// 2E:3E of W, output TRANSPOSED [bh][d][s]).
// ---------------------------------------------------------------------------
__global__ __launch_bounds__(256) void qkv_proj_kernel(
    const float* __restrict__ query, const float* __restrict__ key,
    const float* __restrict__ value, const float* __restrict__ W,
    const float* __restrict__ bias)
{
    const int z = blockIdx.z;
    const float* X  = (z == 0) ? query : (z == 1) ? key : value;
    const float* Wz = W    + ((z == 2) ? 2 * E_DIM * E_DIM : 0);
    const float* bz = bias + ((z == 2) ? 2 * E_DIM : 0);
    const float scale = (z == 0) ? 0.125f * 1.44269504088896340736f : 1.0f;

    __shared__ __align__(16) float Xs[16][64];
    __shared__ __align__(16) float Ws[16][64];

    const int mBase = blockIdx.x * 64, nBase = blockIdx.y * 64;
    const int t = threadIdx.x, tx = t & 15, ty = t >> 4;

    float acc[4][4];
#pragma unroll
    for (int i = 0; i < 4; i++)
#pragma unroll
        for (int j = 0; j < 4; j++) acc[i][j] = 0.0f;

    const int lm = t >> 2, lk = (t & 3) << 2;
    float4 xv = *(const float4*)(X  + (mBase + lm) * E_DIM + lk);
    float4 wv = *(const float4*)(Wz + (nBase + lm) * E_DIM + lk);

    for (int k0 = 0; k0 < E_DIM; k0 += 16) {
        Xs[lk + 0][lm] = xv.x; Xs[lk + 1][lm] = xv.y; Xs[lk + 2][lm] = xv.z; Xs[lk + 3][lm] = xv.w;
        Ws[lk + 0][lm] = wv.x; Ws[lk + 1][lm] = wv.y; Ws[lk + 2][lm] = wv.z; Ws[lk + 3][lm] = wv.w;
        __syncthreads();
        if (k0 + 16 < E_DIM) {
            xv = *(const float4*)(X  + (mBase + lm) * E_DIM + k0 + 16 + lk);
            wv = *(const float4*)(Wz + (nBase + lm) * E_DIM + k0 + 16 + lk);
        }
#pragma unroll
        for (int kk = 0; kk < 16; kk++) {
            float4 a = *(const float4*)&Xs[kk][ty * 4];
            float4 b = *(const float4*)&Ws[kk][tx * 4];
            float av[4] = {a.x, a.y, a.z, a.w};
            float bv[4] = {b.x, b.y, b.z, b.w};
#pragma unroll
            for (int i = 0; i < 4; i++)
#pragma unroll
                for (int j = 0; j < 4; j++) acc[i][j] = fmaf(av[i], bv[j], acc[i][j]);
        }
        __syncthreads();
    }

    const int n0 = nBase + tx * 4, h_ = n0 >> 6, d0 = n0 & 63;
    const float4 bvec = *(const float4*)(bz + n0);
#pragma unroll
    for (int i = 0; i < 4; i++) {
        const int m = mBase + ty * 4 + i, s_ = m >> 2, b_ = m & 3;
        float v[4] = {(acc[i][0] + bvec.x) * scale, (acc[i][1] + bvec.y) * scale,
                      (acc[i][2] + bvec.z) * scale, (acc[i][3] + bvec.w) * scale};
        uint16_t h[4], l[4];
#pragma unroll
        for (int j = 0; j < 4; j++) bf16_split(v[j], h[j], l[j]);
        if (z < 2) {
            __nv_bfloat16* oh = (z == 0) ? g_qh : g_kh;
            __nv_bfloat16* ol = (z == 0) ? g_ql : g_kl;
            const size_t a = ((size_t)(b_ * H_NUM + h_) * S_LEN + s_) * HD + d0;
            *(uint2*)(oh + a) = make_uint2((uint32_t)h[1] << 16 | h[0], (uint32_t)h[3] << 16 | h[2]);
            *(uint2*)(ol + a) = make_uint2((uint32_t)l[1] << 16 | l[0], (uint32_t)l[3] << 16 | l[2]);
        } else {
#pragma unroll
            for (int j = 0; j < 4; j++) {
                const size_t a = ((size_t)(b_ * H_NUM + h_) * HD + d0 + j) * S_LEN + s_;
                g_vh[a] = __ushort_as_bfloat16(h[j]);
                g_vl[a] = __ushort_as_bfloat16(l[j]);
            }
        }
    }
}

// ---------------------------------------------------------------------------
// K/V 64-key tile -> smem (SW128-swizzled 128B rows).
// K rows = key (64 x 64d). V rows = d (64 x 64key), from [bh][d][s].
// ---------------------------------------------------------------------------
__device__ __forceinline__ void load_kv64(char* smem, int bh, int kt, int buf, int t)
{
    const int row = t >> 2, c0 = t & 3;
    {
        const size_t gb = ((size_t)bh * S_LEN + kt * 64 + row) * HD;
        char* dh = smem + SK + buf * 16384;
        char* dl = dh + 8192;
#pragma unroll
        for (int i = 0; i < 2; i++) {
            const int c = c0 + i * 4;
            const uint32_t off = SWZ((uint32_t)(row * 128 + c * 16));
            *(uint4*)(dh + off) = *(const uint4*)(g_kh + gb + c * 8);
            *(uint4*)(dl + off) = *(const uint4*)(g_kl + gb + c * 8);
        }
    }
    {
        const size_t gb = ((size_t)bh * HD + row) * S_LEN + kt * 64;
        char* dh = smem + SV + buf * 16384;
        char* dl = dh + 8192;
#pragma unroll
        for (int i = 0; i < 2; i++) {
            const int c = c0 + i * 4;
            const uint32_t off = SWZ((uint32_t)(row * 128 + c * 16));
            *(uint4*)(dh + off) = *(const uint4*)(g_vh + gb + c * 8);
            *(uint4*)(dl + off) = *(const uint4*)(g_vl + gb + c * 8);
        }
    }
}

// ---------------------------------------------------------------------------
// Flash attention on mma.sync (bf16 hi/lo split, 3 terms per GEMM).
// CTA = (head bh, 128-query tile qt). 8 warps; warp w owns rows w*16..w*16+15.
// ---------------------------------------------------------------------------
__global__ __launch_bounds__(256, 1) void attn_mma()
{
    extern __shared__ char smem[];
    const uint32_t sb = smem_u32(smem);
    const int t = threadIdx.x, w = t >> 5, lane = t & 31;
    const int bh = blockIdx.y, qt = blockIdx.x;

    // stage Q tile (hi/lo) into smem
    {
        const int row = t >> 1, half = t & 1;
        const size_t gb = ((size_t)bh * S_LEN + qt * 128 + row) * HD + half * 32;
#pragma unroll
        for (int c = 0; c < 4; c++) {
            const uint32_t off = SWZ((uint32_t)(row * 128 + half * 64 + c * 16));
            *(uint4*)(smem + SQ_H + off) = *(const uint4*)(g_qh + gb + c * 8);
            *(uint4*)(smem + SQ_L + off) = *(const uint4*)(g_ql + gb + c * 8);
        }
    }
    load_kv64(smem, bh, 0, 0, t);
    __syncthreads();

    // Q fragments (A-layout m16k16): lanes 0-7 rows0-7/k0, 8-15 rows8-15/k0,
    // 16-23 rows0-7/k+16B, 24-31 rows8-15/k+16B
    uint32_t qh[4][4], ql[4][4];
    {
        const int qrow = w * 16 + (lane & 7) + ((lane >> 3) & 1) * 8;
        const int qcb  = ((lane >> 4) & 1) * 16;
#pragma unroll
        for (int ks = 0; ks < 4; ks++) {
            const uint32_t off = SWZ((uint32_t)(qrow * 128 + ks * 32 + qcb));
            ldmx4(qh[ks], sb + SQ_H + off);
            ldmx4(ql[ks], sb + SQ_L + off);
        }
    }

    // B-operand lane addressing (K and V): lanes 0-7 rows0-7/k0, 8-15 rows0-7/
    // k+16B, 16-23 rows8-15/k0, 24-31 rows8-15/k+16B
    const int brow = (lane & 7) + ((lane >> 4) & 1) * 8;
    const int bcb  = ((lane >> 3) & 1) * 16;

    float o[8][4];
#pragma unroll
    for (int n = 0; n < 8; n++)
#pragma unroll
        for (int j = 0; j < 4; j++) o[n][j] = 0.0f;
    float m0 = -1e30f, m1 = -1e30f, l0 = 0.0f, l1 = 0.0f;

    for (int kt = 0; kt < NT64; kt++) {
        const int buf = kt & 1;
        if (kt > 0) __syncthreads();
        if (kt + 1 < NT64) load_kv64(smem, bh, kt + 1, buf ^ 1, t);

        // ---- S = Q K^T ----
        float s[8][4];
#pragma unroll
        for (int n = 0; n < 8; n++)
#pragma unroll
            for (int j = 0; j < 4; j++) s[n][j] = 0.0f;

        const uint32_t kh_b = sb + SK + buf * 16384;
        const uint32_t kl_b = kh_b + 8192;
#pragma unroll
        for (int ks = 0; ks < 4; ks++) {
#pragma unroll
            for (int p = 0; p < 4; p++) {
                const uint32_t off = SWZ((uint32_t)((p * 16 + brow) * 128 + ks * 32 + bcb));
                uint32_t bh4[4], bl4[4];
                ldmx4(bh4, kh_b + off);
                ldmx4(bl4, kl_b + off);
                mma16816(s[2 * p],     qh[ks], bh4);
                mma16816(s[2 * p],     ql[ks], bh4);
                mma16816(s[2 * p],     qh[ks], bl4);
                mma16816(s[2 * p + 1], qh[ks], bh4 + 2);
                mma16816(s[2 * p + 1], ql[ks], bh4 + 2);
                mma16816(s[2 * p + 1], qh[ks], bl4 + 2);
            }
        }

        // ---- online softmax (rows lane>>2 and +8; quad = lanes xor 1,2) ----
        float mx0 = -1e30f, mx1 = -1e30f;
#pragma unroll
        for (int n = 0; n < 8; n++) {
            mx0 = fmaxf(mx0, fmaxf(s[n][0], s[n][1]));
            mx1 = fmaxf(mx1, fmaxf(s[n][2], s[n][3]));
        }
        mx0 = fmaxf(mx0, __shfl_xor_sync(0xffffffffu, mx0, 1));
        mx0 = fmaxf(mx0, __shfl_xor_sync(0xffffffffu, mx0, 2));
        mx1 = fmaxf(mx1, __shfl_xor_sync(0xffffffffu, mx1, 1));
        mx1 = fmaxf(mx1, __shfl_xor_sync(0xffffffffu, mx1, 2));
        const float m0n = fmaxf(m0, mx0), m1n = fmaxf(m1, mx1);
        const float a0 = ex2(m0 - m0n), a1 = ex2(m1 - m1n);
        m0 = m0n; m1 = m1n;

        float s0 = 0.0f, s1 = 0.0f;
#pragma unroll
        for (int n = 0; n < 8; n++) {
            s[n][0] = ex2(s[n][0] - m0n); s[n][1] = ex2(s[n][1] - m0n);
            s[n][2] = ex2(s[n][2] - m1n); s[n][3] = ex2(s[n][3] - m1n);
            s0 += s[n][0] + s[n][1];
            s1 += s[n][2] + s[n][3];
        }
        s0 += __shfl_xor_sync(0xffffffffu, s0, 1);
        s0 += __shfl_xor_sync(0xffffffffu, s0, 2);
        s1 += __shfl_xor_sync(0xffffffffu, s1, 1);
        s1 += __shfl_xor_sync(0xffffffffu, s1, 2);
        l0 = l0 * a0 + s0;
        l1 = l1 * a1 + s1;

#pragma unroll
        for (int n = 0; n < 8; n++) {
            o[n][0] *= a0; o[n][1] *= a0; o[n][2] *= a1; o[n][3] *= a1;
        }

        // ---- pack P (C-frag -> A-frag) ----
        uint32_t ph[4][4], pl[4][4];
#pragma unroll
        for (int ks = 0; ks < 4; ks++) {
            split_pack(s[2 * ks][0],     s[2 * ks][1],     ph[ks][0], pl[ks][0]);
            split_pack(s[2 * ks][2],     s[2 * ks][3],     ph[ks][1], pl[ks][1]);
            split_pack(s[2 * ks + 1][0], s[2 * ks + 1][1], ph[ks][2], pl[ks][2]);
            split_pack(s[2 * ks + 1][2], s[2 * ks + 1][3], ph[ks][3], pl[ks][3]);
        }

        // ---- O += P V ----
        const uint32_t vh_b = sb + SV + buf * 16384;
        const uint32_t vl_b = vh_b + 8192;
#pragma unroll
        for (int ks = 0; ks < 4; ks++) {
#pragma unroll
            for (int p = 0; p < 4; p++) {
                const uint32_t off = SWZ((uint32_t)((p * 16 + brow) * 128 + ks * 32 + bcb));
                uint32_t bh4[4], bl4[4];
                ldmx4(bh4, vh_b + off);
                ldmx4(bl4, vl_b + off);
                mma16816(o[2 * p],     ph[ks], bh4);
                mma16816(o[2 * p],     pl[ks], bh4);
                mma16816(o[2 * p],     ph[ks], bl4);
                mma16816(o[2 * p + 1], ph[ks], bh4 + 2);
                mma16816(o[2 * p + 1], pl[ks], bh4 + 2);
                mma16816(o[2 * p + 1], ph[ks], bl4 + 2);
            }
        }
    }

    // ---- epilogue: normalize + scatter to g_ctx (s*B+b, h*64+d) ----
    const float inv0 = 1.0f / l0, inv1 = 1.0f / l1;
    const int b_ = bh >> 3, h_ = bh & 7;
    const int r0 = qt * 128 + w * 16 + (lane >> 2);
    const int cb = h_ * 64 + 2 * (lane & 3);
#pragma unroll
    for (int n = 0; n < 8; n++) {
        float2 v0 = {o[n][0] * inv0, o[n][1] * inv0};
        float2 v1 = {o[n][2] * inv1, o[n][3] * inv1};
        *(float2*)(g_ctx + ((size_t)r0 * B_SZ + b_) * E_DIM + cb + n * 8) = v0;
        *(float2*)(g_ctx + ((size_t)(r0 + 8) * B_SZ + b_) * E_DIM + cb + n * 8) = v1;
    }
}

// ---------------------------------------------------------------------------
// Output projection (fp32): out = ctx @ Wo^T + bo
// ---------------------------------------------------------------------------
__global__ __launch_bounds__(256) void out_proj_kernel(
    const float* __restrict__ Wo, const float* __restrict__ bo, float* __restrict__ out)
{
    __shared__ __align__(16) float Xs[16][64];
    __shared__ __align__(16) float Ws[16][64];
    const int mBase = blockIdx.x * 64, nBase = blockIdx.y * 64;
    const int t = threadIdx.x, tx = t & 15, ty = t >> 4;

    float acc[4][4];
#pragma unroll
    for (int i = 0; i < 4; i++)
#pragma unroll
        for (int j = 0; j < 4; j++) acc[i][j] = 0.0f;

    const int lm = t >> 2, lk = (t & 3) << 2;
    float4 xv = *(const float4*)(g_ctx + (size_t)(mBase + lm) * E_DIM + lk);
    float4 wv = *(const float4*)(Wo    + (size_t)(nBase + lm) * E_DIM + lk);

    for (int k0 = 0; k0 < E_DIM; k0 += 16) {
        Xs[lk + 0][lm] = xv.x; Xs[lk + 1][lm] = xv.y; Xs[lk + 2][lm] = xv.z; Xs[lk + 3][lm] = xv.w;
        Ws[lk + 0][lm] = wv.x; Ws[lk + 1][lm] = wv.y; Ws[lk + 2][lm] = wv.z; Ws[lk + 3][lm] = wv.w;
        __syncthreads();
        if (k0 + 16 < E_DIM) {
            xv = *(const float4*)(g_ctx + (size_t)(mBase + lm) * E_DIM + k0 + 16 + lk);
            wv = *(const float4*)(Wo    + (size_t)(nBase + lm) * E_DIM + k0 + 16 + lk);
        }
#pragma unroll
        for (int kk = 0; kk < 16; kk++) {
            float4 a = *(const float4*)&Xs[kk][ty * 4];
            float4 b = *(const float4*)&Ws[kk][tx * 4];
            float av[4] = {a.x, a.y, a.z, a.w};
            float bv[4] = {b.x, b.y, b.z, b.w};
#pragma unroll
            for (int i = 0; i < 4; i++)
#pragma unroll
                for (int j = 0; j < 4; j++) acc[i][j] = fmaf(av[i], bv[j], acc[i][j]);
        }
        __syncthreads();
    }

    const int n0 = nBase + tx * 4;
    const float4 bvec = *(const float4*)(bo + n0);
#pragma unroll
    for (int i = 0; i < 4; i++) {
        const int mm = mBase + ty * 4 + i;
        float4 ov = {acc[i][0] + bvec.x, acc[i][1] + bvec.y, acc[i][2] + bvec.z, acc[i][3] + bvec.w};
        *(float4*)(out + (size_t)mm * E_DIM + n0) = ov;
    }
}

extern "C" void kernel_launch(void* const* d_in, const int* in_sizes, int n_in,
                              void* d_out, int out_size)
{
    const float* query = (const float*)d_in[0];
    const float* key   = (const float*)d_in[1];
    const float* value = (const float*)d_in[2];
    const float* in_w  = (const float*)d_in[3];
    const float* in_b  = (const float*)d_in[4];
    const float* out_w = (const float*)d_in[5];
    const float* out_b = (const float*)d_in[6];
    float* out = (float*)d_out;

    static bool attr_set = false;
    if (!attr_set) {
        cudaFuncSetAttribute(attn_mma, cudaFuncAttributeMaxDynamicSharedMemorySize, SMEM_ATTN);
        attr_set = true;
    }

    dim3 projGrid(M_ROWS / 64, E_DIM / 64, 3);
    qkv_proj_kernel<<<projGrid, 256>>>(query, key, value, in_w, in_b);

    dim3 attnGrid(S_LEN / 128, NBH);
    attn_mma<<<attnGrid, 256, SMEM_ATTN>>>();

    dim3 outGrid(M_ROWS / 64, E_DIM / 64);
    out_proj_kernel<<<outGrid, 256>>>(out_w, out_b, out);
}

// round 9
// speedup vs baseline: 3.7464x; 1.4088x over previous
#include <cuda_runtime.h>
#include <cuda_bf16.h>
#include <cstdint>
#include <math.h>

#define S_LEN 2048
#define B_SZ  4
#define E_DIM 512
#define H_NUM 8
#define HD    64
#define M_ROWS (S_LEN * B_SZ)
#define NBH   (B_SZ * H_NUM)
#define NT64  (S_LEN / 64)

// ---------------- scratch ----------------------------------------------------
// converted inputs [m][k] (m = s*B+b, k = e)
__device__ __align__(16) __nv_bfloat16 g_xqh[M_ROWS * E_DIM];
__device__ __align__(16) __nv_bfloat16 g_xql[M_ROWS * E_DIM];
__device__ __align__(16) __nv_bfloat16 g_xkh[M_ROWS * E_DIM];
__device__ __align__(16) __nv_bfloat16 g_xkl[M_ROWS * E_DIM];
__device__ __align__(16) __nv_bfloat16 g_xvh[M_ROWS * E_DIM];
__device__ __align__(16) __nv_bfloat16 g_xvl[M_ROWS * E_DIM];
// converted weights [n][k]
__device__ __align__(16) __nv_bfloat16 g_wqkh[E_DIM * E_DIM];
__device__ __align__(16) __nv_bfloat16 g_wqkl[E_DIM * E_DIM];
__device__ __align__(16) __nv_bfloat16 g_wvh[E_DIM * E_DIM];
__device__ __align__(16) __nv_bfloat16 g_wvl[E_DIM * E_DIM];
__device__ __align__(16) __nv_bfloat16 g_woh[E_DIM * E_DIM];
__device__ __align__(16) __nv_bfloat16 g_wol[E_DIM * E_DIM];
// projected q/k/v, head-major
__device__ __align__(16) __nv_bfloat16 g_qh[NBH * S_LEN * HD];  // [bh][s][d]
__device__ __align__(16) __nv_bfloat16 g_ql[NBH * S_LEN * HD];
__device__ __align__(16) __nv_bfloat16 g_kh[NBH * S_LEN * HD];  // [bh][s][d]
__device__ __align__(16) __nv_bfloat16 g_kl[NBH * S_LEN * HD];
__device__ __align__(16) __nv_bfloat16 g_vh[NBH * S_LEN * HD];  // [bh][d][s]
__device__ __align__(16) __nv_bfloat16 g_vl[NBH * S_LEN * HD];
// attention output ctx, [m][e] bf16 hi/lo
__device__ __align__(16) __nv_bfloat16 g_ch[M_ROWS * E_DIM];
__device__ __align__(16) __nv_bfloat16 g_cl[M_ROWS * E_DIM];

// ---------------- helpers -----------------------------------------------------
__device__ __forceinline__ uint32_t smem_u32(const void* p) {
    uint32_t a;
    asm("{ .reg .u64 t; cvta.to.shared.u64 t, %1; cvt.u32.u64 %0, t; }" : "=r"(a) : "l"(p));
    return a;
}
__device__ __forceinline__ float ex2(float x) {
    float y; asm("ex2.approx.f32 %0, %1;" : "=f"(y) : "f"(x)); return y;
}
__device__ __forceinline__ void ldmx4(uint32_t* r, uint32_t addr) {
    asm volatile("ldmatrix.sync.aligned.m8n8.x4.shared.b16 {%0,%1,%2,%3}, [%4];"
                 : "=r"(r[0]), "=r"(r[1]), "=r"(r[2]), "=r"(r[3]) : "r"(addr));
}
__device__ __forceinline__ void mma16816(float* d, const uint32_t* a, const uint32_t* b) {
    asm volatile("mma.sync.aligned.m16n8k16.row.col.f32.bf16.bf16.f32 "
                 "{%0,%1,%2,%3}, {%4,%5,%6,%7}, {%8,%9}, {%0,%1,%2,%3};"
                 : "+f"(d[0]), "+f"(d[1]), "+f"(d[2]), "+f"(d[3])
                 : "r"(a[0]), "r"(a[1]), "r"(a[2]), "r"(a[3]), "r"(b[0]), "r"(b[1]));
}
__device__ __forceinline__ void split_pack(float v0, float v1, uint32_t& hp, uint32_t& lp) {
    __nv_bfloat16 h0 = __float2bfloat16(v0), h1 = __float2bfloat16(v1);
    float l0 = v0 - __bfloat162float(h0), l1 = v1 - __bfloat162float(h1);
    hp = ((uint32_t)__bfloat16_as_ushort(h1) << 16) | __bfloat16_as_ushort(h0);
    asm("cvt.rn.bf16x2.f32 %0, %1, %2;" : "=r"(lp) : "f"(l1), "f"(l0));
}
#define SWZ(x) ((x) ^ (((x) >> 3) & 0x70))
#define SMEM_BIG 98304

// ---------------------------------------------------------------------------
// Elementwise fp32 -> bf16 hi/lo conversion (z selects src/dst).
// zsel: 0..2 -> inputs (q,k,v), 3..5 -> weights (wqk, wv, wo)
// ---------------------------------------------------------------------------
__global__ void cvt_kernel(const float* __restrict__ s0, const float* __restrict__ s1,
                           const float* __restrict__ s2, int n4, int wsel)
{
    const int z = blockIdx.y;
    const float* src = (z == 0) ? s0 : (z == 1) ? s1 : s2;
    __nv_bfloat16* dh; __nv_bfloat16* dl;
    if (!wsel) { dh = (z == 0) ? g_xqh : (z == 1) ? g_xkh : g_xvh;
                 dl = (z == 0) ? g_xql : (z == 1) ? g_xkl : g_xvl; }
    else       { dh = (z == 0) ? g_wqkh : (z == 1) ? g_wvh : g_woh;
                 dl = (z == 0) ? g_wqkl : (z == 1) ? g_wvl : g_wol; }

    for (int i = blockIdx.x * blockDim.x + threadIdx.x; i < n4; i += gridDim.x * blockDim.x) {
        float4 v = ((const float4*)src)[i];
        uint32_t h0, l0, h1, l1;
        split_pack(v.x, v.y, h0, l0);
        split_pack(v.z, v.w, h1, l1);
        ((uint2*)dh)[i] = make_uint2(h0, h1);
        ((uint2*)dl)[i] = make_uint2(l0, l1);
    }
}

// ---------------------------------------------------------------------------
// mma.sync GEMM: C[M,N] = A[M,K] @ B[N,K]^T, hi/lo split (3 terms).
// BM=128, BN=64, BK=64, 256 threads (8 warps: 4 along M x 2 along N).
// mode 0: q epilogue (bias, scale, head-major bf16 hi/lo)
// mode 1: k epilogue (bias, head-major)
// mode 2: v epilogue (bias, transposed [bh][d][s])
// mode 3: out epilogue (bias, fp32 to out)
// ---------------------------------------------------------------------------
__global__ __launch_bounds__(256, 1) void gemm_mma(
    const float* __restrict__ in_b, const float* __restrict__ out_b,
    float* __restrict__ outp, int qkv)
{
    extern __shared__ char smem[];
    const uint32_t sb = smem_u32(smem);
    const int mode = qkv ? blockIdx.z : 3;

    const __nv_bfloat16 *Ah, *Al, *Bh, *Bl;
    const float* bias;
    switch (mode) {
        case 0:  Ah = g_xqh; Al = g_xql; Bh = g_wqkh; Bl = g_wqkl; bias = in_b; break;
        case 1:  Ah = g_xkh; Al = g_xkl; Bh = g_wqkh; Bl = g_wqkl; bias = in_b; break;
        case 2:  Ah = g_xvh; Al = g_xvl; Bh = g_wvh;  Bl = g_wvl;  bias = in_b + 2 * E_DIM; break;
        default: Ah = g_ch;  Al = g_cl;  Bh = g_woh;  Bl = g_wol;  bias = out_b; break;
    }
    const float scale = (mode == 0) ? 0.125f * 1.44269504088896340736f : 1.0f;

    const int mBase = blockIdx.x * 128, nBase = blockIdx.y * 64;
    const int t = threadIdx.x, w = t >> 5, lane = t & 31;
    const int wm = w & 3, wn = w >> 2;

    // tile loader (SW128-swizzled 128B rows)
    auto load_tile = [&](int buf, int k0) {
        char* da = smem + buf * 49152;
        {   // A: 128 rows x 64 k (hi + lo)
            const int row = t >> 1, half = t & 1;
            const size_t gb = (size_t)(mBase + row) * E_DIM + k0 + half * 32;
#pragma unroll
            for (int i = 0; i < 4; i++) {
                const uint32_t off = SWZ((uint32_t)(row * 128 + half * 64 + i * 16));
                *(uint4*)(da + off)         = *(const uint4*)(Ah + gb + i * 8);
                *(uint4*)(da + 16384 + off) = *(const uint4*)(Al + gb + i * 8);
            }
        }
        {   // B: 64 rows x 64 k (hi + lo)
            const int row = t >> 2, q = t & 3;
            const size_t gb = (size_t)(nBase + row) * E_DIM + k0;
            char* db = da + 32768;
#pragma unroll
            for (int i = 0; i < 2; i++) {
                const int j = q + i * 4;
                const uint32_t off = SWZ((uint32_t)(row * 128 + j * 16));
                *(uint4*)(db + off)        = *(const uint4*)(Bh + gb + j * 8);
                *(uint4*)(db + 8192 + off) = *(const uint4*)(Bl + gb + j * 8);
            }
        }
    };

    load_tile(0, 0);
    __syncthreads();

    float acc[2][4][4];
#pragma unroll
    for (int a = 0; a < 2; a++)
#pragma unroll
        for (int b = 0; b < 4; b++)
#pragma unroll
            for (int c = 0; c < 4; c++) acc[a][b][c] = 0.0f;

    const int arow = wm * 32 + (lane & 7) + ((lane >> 3) & 1) * 8;
    const int acb  = ((lane >> 4) & 1) * 16;
    const int brow = wn * 32 + (lane & 7) + ((lane >> 4) & 1) * 8;
    const int bcb  = ((lane >> 3) & 1) * 16;

    for (int kc = 0; kc < E_DIM / 64; kc++) {
        const int buf = kc & 1;
        if (kc + 1 < E_DIM / 64) load_tile(buf ^ 1, (kc + 1) * 64);

        const uint32_t AH = sb + buf * 49152;
        const uint32_t AL = AH + 16384;
        const uint32_t BH = AH + 32768;
        const uint32_t BL = BH + 8192;
#pragma unroll
        for (int ks = 0; ks < 4; ks++) {
            uint32_t ah0[4], al0[4], ah1[4], al1[4];
            ldmx4(ah0, AH + SWZ((uint32_t)(arow * 128 + ks * 32 + acb)));
            ldmx4(ah1, AH + SWZ((uint32_t)((arow + 16) * 128 + ks * 32 + acb)));
            ldmx4(al0, AL + SWZ((uint32_t)(arow * 128 + ks * 32 + acb)));
            ldmx4(al1, AL + SWZ((uint32_t)((arow + 16) * 128 + ks * 32 + acb)));
#pragma unroll
            for (int n2 = 0; n2 < 2; n2++) {
                uint32_t bh4[4], bl4[4];
                const uint32_t boff = SWZ((uint32_t)((brow + n2 * 16) * 128 + ks * 32 + bcb));
                ldmx4(bh4, BH + boff);
                ldmx4(bl4, BL + boff);
#pragma unroll
                for (int h = 0; h < 2; h++) {
                    float* d0 = acc[0][n2 * 2 + h];
                    float* d1 = acc[1][n2 * 2 + h];
                    mma16816(d0, ah0, bh4 + 2 * h);
                    mma16816(d0, al0, bh4 + 2 * h);
                    mma16816(d0, ah0, bl4 + 2 * h);
                    mma16816(d1, ah1, bh4 + 2 * h);
                    mma16816(d1, al1, bh4 + 2 * h);
                    mma16816(d1, ah1, bl4 + 2 * h);
                }
            }
        }
        __syncthreads();
    }

    // ---- epilogue ----
#pragma unroll
    for (int mi = 0; mi < 2; mi++) {
#pragma unroll
        for (int nj = 0; nj < 4; nj++) {
            const int r0 = mBase + wm * 32 + mi * 16 + (lane >> 2);
            const int c  = nBase + wn * 32 + nj * 8 + 2 * (lane & 3);
            const float2 bv = *(const float2*)(bias + c);
            float v00 = (acc[mi][nj][0] + bv.x) * scale;
            float v01 = (acc[mi][nj][1] + bv.y) * scale;
            float v10 = (acc[mi][nj][2] + bv.x) * scale;
            float v11 = (acc[mi][nj][3] + bv.y) * scale;
            if (mode == 3) {
                *(float2*)(outp + (size_t)r0 * E_DIM + c)       = make_float2(v00, v01);
                *(float2*)(outp + (size_t)(r0 + 8) * E_DIM + c) = make_float2(v10, v11);
            } else {
                const int h_ = c >> 6, d = c & 63;
                const int s0 = r0 >> 2, b0 = r0 & 3;
                const int s1 = (r0 + 8) >> 2, b1 = (r0 + 8) & 3;
                uint32_t hp0, lp0, hp1, lp1;
                split_pack(v00, v01, hp0, lp0);
                split_pack(v10, v11, hp1, lp1);
                if (mode < 2) {
                    __nv_bfloat16* oh = (mode == 0) ? g_qh : g_kh;
                    __nv_bfloat16* ol = (mode == 0) ? g_ql : g_kl;
                    const size_t a0 = ((size_t)(b0 * H_NUM + h_) * S_LEN + s0) * HD + d;
                    const size_t a1 = ((size_t)(b1 * H_NUM + h_) * S_LEN + s1) * HD + d;
                    *(uint32_t*)(oh + a0) = hp0; *(uint32_t*)(ol + a0) = lp0;
                    *(uint32_t*)(oh + a1) = hp1; *(uint32_t*)(ol + a1) = lp1;
                } else {
                    const size_t base0 = ((size_t)(b0 * H_NUM + h_) * HD + d) * S_LEN + s0;
                    const size_t base1 = ((size_t)(b1 * H_NUM + h_) * HD + d) * S_LEN + s1;
                    g_vh[base0] = __ushort_as_bfloat16((uint16_t)hp0);
                    g_vh[base0 + S_LEN] = __ushort_as_bfloat16((uint16_t)(hp0 >> 16));
                    g_vl[base0] = __ushort_as_bfloat16((uint16_t)lp0);
                    g_vl[base0 + S_LEN] = __ushort_as_bfloat16((uint16_t)(lp0 >> 16));
                    g_vh[base1] = __ushort_as_bfloat16((uint16_t)hp1);
                    g_vh[base1 + S_LEN] = __ushort_as_bfloat16((uint16_t)(hp1 >> 16));
                    g_vl[base1] = __ushort_as_bfloat16((uint16_t)lp1);
                    g_vl[base1 + S_LEN] = __ushort_as_bfloat16((uint16_t)(lp1 >> 16));
                }
            }
        }
    }
}

// ---------------------------------------------------------------------------
// K/V 64-key tile -> smem (SW128-swizzled 128B rows).
// ---------------------------------------------------------------------------
#define SQ_H 0
#define SQ_L 16384
#define SK   32768
#define SV   65536

__device__ __forceinline__ void load_kv64(char* smem, int bh, int kt, int buf, int t)
{
    const int row = t >> 2, c0 = t & 3;
    {
        const size_t gb = ((size_t)bh * S_LEN + kt * 64 + row) * HD;
        char* dh = smem + SK + buf * 16384;
        char* dl = dh + 8192;
#pragma unroll
        for (int i = 0; i < 2; i++) {
            const int c = c0 + i * 4;
            const uint32_t off = SWZ((uint32_t)(row * 128 + c * 16));
            *(uint4*)(dh + off) = *(const uint4*)(g_kh + gb + c * 8);
            *(uint4*)(dl + off) = *(const uint4*)(g_kl + gb + c * 8);
        }
    }
    {
        const size_t gb = ((size_t)bh * HD + row) * S_LEN + kt * 64;
        char* dh = smem + SV + buf * 16384;
        char* dl = dh + 8192;
#pragma unroll
        for (int i = 0; i < 2; i++) {
            const int c = c0 + i * 4;
            const uint32_t off = SWZ((uint32_t)(row * 128 + c * 16));
            *(uint4*)(dh + off) = *(const uint4*)(g_vh + gb + c * 8);
            *(uint4*)(dl + off) = *(const uint4*)(g_vl + gb + c * 8);
        }
    }
}

// ---------------------------------------------------------------------------
// Flash attention on mma.sync (hi/lo split). CTA = (head, 128-query tile).
// ---------------------------------------------------------------------------
__global__ __launch_bounds__(256, 1) void attn_mma()
{
    extern __shared__ char smem[];
    const uint32_t sb = smem_u32(smem);
    const int t = threadIdx.x, w = t >> 5, lane = t & 31;
    const int bh = blockIdx.y, qt = blockIdx.x;

    {
        const int row = t >> 1, half = t & 1;
        const size_t gb = ((size_t)bh * S_LEN + qt * 128 + row) * HD + half * 32;
#pragma unroll
        for (int c = 0; c < 4; c++) {
            const uint32_t off = SWZ((uint32_t)(row * 128 + half * 64 + c * 16));
            *(uint4*)(smem + SQ_H + off) = *(const uint4*)(g_qh + gb + c * 8);
            *(uint4*)(smem + SQ_L + off) = *(const uint4*)(g_ql + gb + c * 8);
        }
    }
    load_kv64(smem, bh, 0, 0, t);
    __syncthreads();

    uint32_t qh[4][4], ql[4][4];
    {
        const int qrow = w * 16 + (lane & 7) + ((lane >> 3) & 1) * 8;
        const int qcb  = ((lane >> 4) & 1) * 16;
#pragma unroll
        for (int ks = 0; ks < 4; ks++) {
            const uint32_t off = SWZ((uint32_t)(qrow * 128 + ks * 32 + qcb));
            ldmx4(qh[ks], sb + SQ_H + off);
            ldmx4(ql[ks], sb + SQ_L + off);
        }
    }

    const int brow = (lane & 7) + ((lane >> 4) & 1) * 8;
    const int bcb  = ((lane >> 3) & 1) * 16;

    float o[8][4];
#pragma unroll
    for (int n = 0; n < 8; n++)
#pragma unroll
        for (int j = 0; j < 4; j++) o[n][j] = 0.0f;
    float m0 = -1e30f, m1 = -1e30f, l0 = 0.0f, l1 = 0.0f;

    for (int kt = 0; kt < NT64; kt++) {
        const int buf = kt & 1;
        if (kt > 0) __syncthreads();
        if (kt + 1 < NT64) load_kv64(smem, bh, kt + 1, buf ^ 1, t);

        float s[8][4];
#pragma unroll
        for (int n = 0; n < 8; n++)
#pragma unroll
            for (int j = 0; j < 4; j++) s[n][j] = 0.0f;

        const uint32_t kh_b = sb + SK + buf * 16384;
        const uint32_t kl_b = kh_b + 8192;
#pragma unroll
        for (int ks = 0; ks < 4; ks++) {
#pragma unroll
            for (int p = 0; p < 4; p++) {
                const uint32_t off = SWZ((uint32_t)((p * 16 + brow) * 128 + ks * 32 + bcb));
                uint32_t bh4[4], bl4[4];
                ldmx4(bh4, kh_b + off);
                ldmx4(bl4, kl_b + off);
                mma16816(s[2 * p],     qh[ks], bh4);
                mma16816(s[2 * p],     ql[ks], bh4);
                mma16816(s[2 * p],     qh[ks], bl4);
                mma16816(s[2 * p + 1], qh[ks], bh4 + 2);
                mma16816(s[2 * p + 1], ql[ks], bh4 + 2);
                mma16816(s[2 * p + 1], qh[ks], bl4 + 2);
            }
        }

        float mx0 = -1e30f, mx1 = -1e30f;
#pragma unroll
        for (int n = 0; n < 8; n++) {
            mx0 = fmaxf(mx0, fmaxf(s[n][0], s[n][1]));
            mx1 = fmaxf(mx1, fmaxf(s[n][2], s[n][3]));
        }
        mx0 = fmaxf(mx0, __shfl_xor_sync(0xffffffffu, mx0, 1));
        mx0 = fmaxf(mx0, __shfl_xor_sync(0xffffffffu, mx0, 2));
        mx1 = fmaxf(mx1, __shfl_xor_sync(0xffffffffu, mx1, 1));
        mx1 = fmaxf(mx1, __shfl_xor_sync(0xffffffffu, mx1, 2));
        const float m0n = fmaxf(m0, mx0), m1n = fmaxf(m1, mx1);
        const float a0 = ex2(m0 - m0n), a1 = ex2(m1 - m1n);
        m0 = m0n; m1 = m1n;

        float s0 = 0.0f, s1 = 0.0f;
#pragma unroll
        for (int n = 0; n < 8; n++) {
            s[n][0] = ex2(s[n][0] - m0n); s[n][1] = ex2(s[n][1] - m0n);
            s[n][2] = ex2(s[n][2] - m1n); s[n][3] = ex2(s[n][3] - m1n);
            s0 += s[n][0] + s[n][1];
            s1 += s[n][2] + s[n][3];
        }
        s0 += __shfl_xor_sync(0xffffffffu, s0, 1);
        s0 += __shfl_xor_sync(0xffffffffu, s0, 2);
        s1 += __shfl_xor_sync(0xffffffffu, s1, 1);
        s1 += __shfl_xor_sync(0xffffffffu, s1, 2);
        l0 = l0 * a0 + s0;
        l1 = l1 * a1 + s1;

#pragma unroll
        for (int n = 0; n < 8; n++) {
            o[n][0] *= a0; o[n][1] *= a0; o[n][2] *= a1; o[n][3] *= a1;
        }

        uint32_t ph[4][4], pl[4][4];
#pragma unroll
        for (int ks = 0; ks < 4; ks++) {
            split_pack(s[2 * ks][0],     s[2 * ks][1],     ph[ks][0], pl[ks][0]);
            split_pack(s[2 * ks][2],     s[2 * ks][3],     ph[ks][1], pl[ks][1]);
            split_pack(s[2 * ks + 1][0], s[2 * ks + 1][1], ph[ks][2], pl[ks][2]);
            split_pack(s[2 * ks + 1][2], s[2 * ks + 1][3], ph[ks][3], pl[ks][3]);
        }

        const uint32_t vh_b = sb + SV + buf * 16384;
        const uint32_t vl_b = vh_b + 8192;
#pragma unroll
        for (int ks = 0; ks < 4; ks++) {
#pragma unroll
            for (int p = 0; p < 4; p++) {
                const uint32_t off = SWZ((uint32_t)((p * 16 + brow) * 128 + ks * 32 + bcb));
                uint32_t bh4[4], bl4[4];
                ldmx4(bh4, vh_b + off);
                ldmx4(bl4, vl_b + off);
                mma16816(o[2 * p],     ph[ks], bh4);
                mma16816(o[2 * p],     pl[ks], bh4);
                mma16816(o[2 * p],     ph[ks], bl4);
                mma16816(o[2 * p + 1], ph[ks], bh4 + 2);
                mma16816(o[2 * p + 1], pl[ks], bh4 + 2);
                mma16816(o[2 * p + 1], ph[ks], bl4 + 2);
            }
        }
    }

    // epilogue: normalize, split to bf16 hi/lo ctx [m][e]
    const float inv0 = 1.0f / l0, inv1 = 1.0f / l1;
    const int b_ = bh >> 3, h_ = bh & 7;
    const int r0 = qt * 128 + w * 16 + (lane >> 2);
    const int cb = h_ * 64 + 2 * (lane & 3);
#pragma unroll
    for (int n = 0; n < 8; n++) {
        uint32_t hp, lp;
        const size_t i0 = ((size_t)r0 * B_SZ + b_) * E_DIM + cb + n * 8;
        const size_t i1 = ((size_t)(r0 + 8) * B_SZ + b_) * E_DIM + cb + n * 8;
        split_pack(o[n][0] * inv0, o[n][1] * inv0, hp, lp);
        *(uint32_t*)(g_ch + i0) = hp; *(uint32_t*)(g_cl + i0) = lp;
        split_pack(o[n][2] * inv1, o[n][3] * inv1, hp, lp);
        *(uint32_t*)(g_ch + i1) = hp; *(uint32_t*)(g_cl + i1) = lp;
    }
}

extern "C" void kernel_launch(void* const* d_in, const int* in_sizes, int n_in,
                              void* d_out, int out_size)
{
    const float* query = (const float*)d_in[0];
    const float* key   = (const float*)d_in[1];
    const float* value = (const float*)d_in[2];
    const float* in_w  = (const float*)d_in[3];
    const float* in_b  = (const float*)d_in[4];
    const float* out_w = (const float*)d_in[5];
    const float* out_b = (const float*)d_in[6];
    float* out = (float*)d_out;

    static bool attr_set = false;
    if (!attr_set) {
        cudaFuncSetAttribute(attn_mma, cudaFuncAttributeMaxDynamicSharedMemorySize, SMEM_BIG);
        cudaFuncSetAttribute(gemm_mma, cudaFuncAttributeMaxDynamicSharedMemorySize, SMEM_BIG);
        attr_set = true;
    }

    // convert inputs and weights to bf16 hi/lo
    cvt_kernel<<<dim3(1024, 3), 256>>>(query, key, value, M_ROWS * E_DIM / 4, 0);
    cvt_kernel<<<dim3(256, 3), 256>>>(in_w, in_w + 2 * E_DIM * E_DIM, out_w,
                                      E_DIM * E_DIM / 4, 1);

    // QKV projection (tensor cores)
    gemm_mma<<<dim3(M_ROWS / 128, E_DIM / 64, 3), 256, SMEM_BIG>>>(in_b, out_b, out, 1);

    // attention
    attn_mma<<<dim3(S_LEN / 128, NBH), 256, SMEM_BIG>>>();

    // output projection (tensor cores)
    gemm_mma<<<dim3(M_ROWS / 128, E_DIM / 64, 1), 256, SMEM_BIG>>>(in_b, out_b, out, 0);
}

// round 10
// speedup vs baseline: 3.9916x; 1.0654x over previous
#include <cuda_runtime.h>
#include <cuda_bf16.h>
#include <cstdint>
#include <math.h>

#define S_LEN 2048
#define B_SZ  4
#define E_DIM 512
#define H_NUM 8
#define HD    64
#define M_ROWS (S_LEN * B_SZ)
#define NBH   (B_SZ * H_NUM)
#define NT64  (S_LEN / 64)

// ---------------- scratch ----------------------------------------------------
__device__ __align__(16) __nv_bfloat16 g_xqh[M_ROWS * E_DIM];
__device__ __align__(16) __nv_bfloat16 g_xql[M_ROWS * E_DIM];
__device__ __align__(16) __nv_bfloat16 g_xkh[M_ROWS * E_DIM];
__device__ __align__(16) __nv_bfloat16 g_xkl[M_ROWS * E_DIM];
__device__ __align__(16) __nv_bfloat16 g_xvh[M_ROWS * E_DIM];
__device__ __align__(16) __nv_bfloat16 g_xvl[M_ROWS * E_DIM];
__device__ __align__(16) __nv_bfloat16 g_wqkh[E_DIM * E_DIM];
__device__ __align__(16) __nv_bfloat16 g_wqkl[E_DIM * E_DIM];
__device__ __align__(16) __nv_bfloat16 g_wvh[E_DIM * E_DIM];
__device__ __align__(16) __nv_bfloat16 g_wvl[E_DIM * E_DIM];
__device__ __align__(16) __nv_bfloat16 g_woh[E_DIM * E_DIM];
__device__ __align__(16) __nv_bfloat16 g_wol[E_DIM * E_DIM];
__device__ __align__(16) __nv_bfloat16 g_qh[NBH * S_LEN * HD];  // [bh][s][d]
__device__ __align__(16) __nv_bfloat16 g_ql[NBH * S_LEN * HD];
__device__ __align__(16) __nv_bfloat16 g_kh[NBH * S_LEN * HD];  // [bh][s][d]
__device__ __align__(16) __nv_bfloat16 g_kl[NBH * S_LEN * HD];
__device__ __align__(16) __nv_bfloat16 g_vh[NBH * S_LEN * HD];  // [bh][d][s]
__device__ __align__(16) __nv_bfloat16 g_vl[NBH * S_LEN * HD];
__device__ __align__(16) __nv_bfloat16 g_ch[M_ROWS * E_DIM];
__device__ __align__(16) __nv_bfloat16 g_cl[M_ROWS * E_DIM];

// ---------------- helpers -----------------------------------------------------
__device__ __forceinline__ uint32_t smem_u32(const void* p) {
    uint32_t a;
    asm("{ .reg .u64 t; cvta.to.shared.u64 t, %1; cvt.u32.u64 %0, t; }" : "=r"(a) : "l"(p));
    return a;
}
__device__ __forceinline__ float ex2(float x) {
    float y; asm("ex2.approx.f32 %0, %1;" : "=f"(y) : "f"(x)); return y;
}
__device__ __forceinline__ void ldmx4(uint32_t* r, uint32_t addr) {
    asm volatile("ldmatrix.sync.aligned.m8n8.x4.shared.b16 {%0,%1,%2,%3}, [%4];"
                 : "=r"(r[0]), "=r"(r[1]), "=r"(r[2]), "=r"(r[3]) : "r"(addr));
}
__device__ __forceinline__ void mma16816(float* d, const uint32_t* a, const uint32_t* b) {
    asm volatile("mma.sync.aligned.m16n8k16.row.col.f32.bf16.bf16.f32 "
                 "{%0,%1,%2,%3}, {%4,%5,%6,%7}, {%8,%9}, {%0,%1,%2,%3};"
                 : "+f"(d[0]), "+f"(d[1]), "+f"(d[2]), "+f"(d[3])
                 : "r"(a[0]), "r"(a[1]), "r"(a[2]), "r"(a[3]), "r"(b[0]), "r"(b[1]));
}
__device__ __forceinline__ void split_pack(float v0, float v1, uint32_t& hp, uint32_t& lp) {
    __nv_bfloat16 h0 = __float2bfloat16(v0), h1 = __float2bfloat16(v1);
    float l0 = v0 - __bfloat162float(h0), l1 = v1 - __bfloat162float(h1);
    hp = ((uint32_t)__bfloat16_as_ushort(h1) << 16) | __bfloat16_as_ushort(h0);
    asm("cvt.rn.bf16x2.f32 %0, %1, %2;" : "=r"(lp) : "f"(l1), "f"(l0));
}
#define SWZ(x) ((x) ^ (((x) >> 3) & 0x70))
#define SMEM_BIG 98304

// ---------------------------------------------------------------------------
// Elementwise fp32 -> bf16 hi/lo conversion.
// ---------------------------------------------------------------------------
__global__ void cvt_kernel(const float* __restrict__ s0, const float* __restrict__ s1,
                           const float* __restrict__ s2, int n4, int wsel)
{
    const int z = blockIdx.y;
    const float* src = (z == 0) ? s0 : (z == 1) ? s1 : s2;
    __nv_bfloat16* dh; __nv_bfloat16* dl;
    if (!wsel) { dh = (z == 0) ? g_xqh : (z == 1) ? g_xkh : g_xvh;
                 dl = (z == 0) ? g_xql : (z == 1) ? g_xkl : g_xvl; }
    else       { dh = (z == 0) ? g_wqkh : (z == 1) ? g_wvh : g_woh;
                 dl = (z == 0) ? g_wqkl : (z == 1) ? g_wvl : g_wol; }

    for (int i = blockIdx.x * blockDim.x + threadIdx.x; i < n4; i += gridDim.x * blockDim.x) {
        float4 v = ((const float4*)src)[i];
        uint32_t h0, l0, h1, l1;
        split_pack(v.x, v.y, h0, l0);
        split_pack(v.z, v.w, h1, l1);
        ((uint2*)dh)[i] = make_uint2(h0, h1);
        ((uint2*)dl)[i] = make_uint2(l0, l1);
    }
}

// ---------------------------------------------------------------------------
// mma.sync GEMM: C[M,N] = A[M,K] @ B[N,K]^T, hi/lo split (3 terms).
// ---------------------------------------------------------------------------
__global__ __launch_bounds__(256, 1) void gemm_mma(
    const float* __restrict__ in_b, const float* __restrict__ out_b,
    float* __restrict__ outp, int qkv)
{
    extern __shared__ char smem[];
    const uint32_t sb = smem_u32(smem);
    const int mode = qkv ? blockIdx.z : 3;

    const __nv_bfloat16 *Ah, *Al, *Bh, *Bl;
    const float* bias;
    switch (mode) {
        case 0:  Ah = g_xqh; Al = g_xql; Bh = g_wqkh; Bl = g_wqkl; bias = in_b; break;
        case 1:  Ah = g_xkh; Al = g_xkl; Bh = g_wqkh; Bl = g_wqkl; bias = in_b; break;
        case 2:  Ah = g_xvh; Al = g_xvl; Bh = g_wvh;  Bl = g_wvl;  bias = in_b + 2 * E_DIM; break;
        default: Ah = g_ch;  Al = g_cl;  Bh = g_woh;  Bl = g_wol;  bias = out_b; break;
    }
    const float scale = (mode == 0) ? 0.125f * 1.44269504088896340736f : 1.0f;

    const int mBase = blockIdx.x * 128, nBase = blockIdx.y * 64;
    const int t = threadIdx.x, w = t >> 5, lane = t & 31;
    const int wm = w & 3, wn = w >> 2;

    auto load_tile = [&](int buf, int k0) {
        char* da = smem + buf * 49152;
        {
            const int row = t >> 1, half = t & 1;
            const size_t gb = (size_t)(mBase + row) * E_DIM + k0 + half * 32;
#pragma unroll
            for (int i = 0; i < 4; i++) {
                const uint32_t off = SWZ((uint32_t)(row * 128 + half * 64 + i * 16));
                *(uint4*)(da + off)         = *(const uint4*)(Ah + gb + i * 8);
                *(uint4*)(da + 16384 + off) = *(const uint4*)(Al + gb + i * 8);
            }
        }
        {
            const int row = t >> 2, q = t & 3;
            const size_t gb = (size_t)(nBase + row) * E_DIM + k0;
            char* db = da + 32768;
#pragma unroll
            for (int i = 0; i < 2; i++) {
                const int j = q + i * 4;
                const uint32_t off = SWZ((uint32_t)(row * 128 + j * 16));
                *(uint4*)(db + off)        = *(const uint4*)(Bh + gb + j * 8);
                *(uint4*)(db + 8192 + off) = *(const uint4*)(Bl + gb + j * 8);
            }
        }
    };

    load_tile(0, 0);
    __syncthreads();

    float acc[2][4][4];
#pragma unroll
    for (int a = 0; a < 2; a++)
#pragma unroll
        for (int b = 0; b < 4; b++)
#pragma unroll
            for (int c = 0; c < 4; c++) acc[a][b][c] = 0.0f;

    const int arow = wm * 32 + (lane & 7) + ((lane >> 3) & 1) * 8;
    const int acb  = ((lane >> 4) & 1) * 16;
    const int brow = wn * 32 + (lane & 7) + ((lane >> 4) & 1) * 8;
    const int bcb  = ((lane >> 3) & 1) * 16;

    for (int kc = 0; kc < E_DIM / 64; kc++) {
        const int buf = kc & 1;
        if (kc + 1 < E_DIM / 64) load_tile(buf ^ 1, (kc + 1) * 64);

        const uint32_t AH = sb + buf * 49152;
        const uint32_t AL = AH + 16384;
        const uint32_t BH = AH + 32768;
        const uint32_t BL = BH + 8192;
#pragma unroll
        for (int ks = 0; ks < 4; ks++) {
            uint32_t ah0[4], al0[4], ah1[4], al1[4];
            ldmx4(ah0, AH + SWZ((uint32_t)(arow * 128 + ks * 32 + acb)));
            ldmx4(ah1, AH + SWZ((uint32_t)((arow + 16) * 128 + ks * 32 + acb)));
            ldmx4(al0, AL + SWZ((uint32_t)(arow * 128 + ks * 32 + acb)));
            ldmx4(al1, AL + SWZ((uint32_t)((arow + 16) * 128 + ks * 32 + acb)));
#pragma unroll
            for (int n2 = 0; n2 < 2; n2++) {
                uint32_t bh4[4], bl4[4];
                const uint32_t boff = SWZ((uint32_t)((brow + n2 * 16) * 128 + ks * 32 + bcb));
                ldmx4(bh4, BH + boff);
                ldmx4(bl4, BL + boff);
#pragma unroll
                for (int h = 0; h < 2; h++) {
                    float* d0 = acc[0][n2 * 2 + h];
                    float* d1 = acc[1][n2 * 2 + h];
                    mma16816(d0, ah0, bh4 + 2 * h);
                    mma16816(d0, al0, bh4 + 2 * h);
                    mma16816(d0, ah0, bl4 + 2 * h);
                    mma16816(d1, ah1, bh4 + 2 * h);
                    mma16816(d1, al1, bh4 + 2 * h);
                    mma16816(d1, ah1, bl4 + 2 * h);
                }
            }
        }
        __syncthreads();
    }

#pragma unroll
    for (int mi = 0; mi < 2; mi++) {
#pragma unroll
        for (int nj = 0; nj < 4; nj++) {
            const int r0 = mBase + wm * 32 + mi * 16 + (lane >> 2);
            const int c  = nBase + wn * 32 + nj * 8 + 2 * (lane & 3);
            const float2 bv = *(const float2*)(bias + c);
            float v00 = (acc[mi][nj][0] + bv.x) * scale;
            float v01 = (acc[mi][nj][1] + bv.y) * scale;
            float v10 = (acc[mi][nj][2] + bv.x) * scale;
            float v11 = (acc[mi][nj][3] + bv.y) * scale;
            if (mode == 3) {
                *(float2*)(outp + (size_t)r0 * E_DIM + c)       = make_float2(v00, v01);
                *(float2*)(outp + (size_t)(r0 + 8) * E_DIM + c) = make_float2(v10, v11);
            } else {
                const int h_ = c >> 6, d = c & 63;
                const int s0 = r0 >> 2, b0 = r0 & 3;
                const int s1 = (r0 + 8) >> 2, b1 = (r0 + 8) & 3;
                uint32_t hp0, lp0, hp1, lp1;
                split_pack(v00, v01, hp0, lp0);
                split_pack(v10, v11, hp1, lp1);
                if (mode < 2) {
                    __nv_bfloat16* oh = (mode == 0) ? g_qh : g_kh;
                    __nv_bfloat16* ol = (mode == 0) ? g_ql : g_kl;
                    const size_t a0 = ((size_t)(b0 * H_NUM + h_) * S_LEN + s0) * HD + d;
                    const size_t a1 = ((size_t)(b1 * H_NUM + h_) * S_LEN + s1) * HD + d;
                    *(uint32_t*)(oh + a0) = hp0; *(uint32_t*)(ol + a0) = lp0;
                    *(uint32_t*)(oh + a1) = hp1; *(uint32_t*)(ol + a1) = lp1;
                } else {
                    const size_t base0 = ((size_t)(b0 * H_NUM + h_) * HD + d) * S_LEN + s0;
                    const size_t base1 = ((size_t)(b1 * H_NUM + h_) * HD + d) * S_LEN + s1;
                    g_vh[base0] = __ushort_as_bfloat16((uint16_t)hp0);
                    g_vh[base0 + S_LEN] = __ushort_as_bfloat16((uint16_t)(hp0 >> 16));
                    g_vl[base0] = __ushort_as_bfloat16((uint16_t)lp0);
                    g_vl[base0 + S_LEN] = __ushort_as_bfloat16((uint16_t)(lp0 >> 16));
                    g_vh[base1] = __ushort_as_bfloat16((uint16_t)hp1);
                    g_vh[base1 + S_LEN] = __ushort_as_bfloat16((uint16_t)(hp1 >> 16));
                    g_vl[base1] = __ushort_as_bfloat16((uint16_t)lp1);
                    g_vl[base1 + S_LEN] = __ushort_as_bfloat16((uint16_t)(lp1 >> 16));
                }
            }
        }
    }
}

// ---------------------------------------------------------------------------
// K/V 64-key tile -> smem (SW128-swizzled 128B rows).
// ---------------------------------------------------------------------------
#define SQ_H 0
#define SQ_L 16384
#define SK   32768
#define SV   65536

__device__ __forceinline__ void load_kv64(char* smem, int bh, int kt, int buf, int t)
{
    const int row = t >> 2, c0 = t & 3;
    {
        const size_t gb = ((size_t)bh * S_LEN + kt * 64 + row) * HD;
        char* dh = smem + SK + buf * 16384;
        char* dl = dh + 8192;
#pragma unroll
        for (int i = 0; i < 2; i++) {
            const int c = c0 + i * 4;
            const uint32_t off = SWZ((uint32_t)(row * 128 + c * 16));
            *(uint4*)(dh + off) = *(const uint4*)(g_kh + gb + c * 8);
            *(uint4*)(dl + off) = *(const uint4*)(g_kl + gb + c * 8);
        }
    }
    {
        const size_t gb = ((size_t)bh * HD + row) * S_LEN + kt * 64;
        char* dh = smem + SV + buf * 16384;
        char* dl = dh + 8192;
#pragma unroll
        for (int i = 0; i < 2; i++) {
            const int c = c0 + i * 4;
            const uint32_t off = SWZ((uint32_t)(row * 128 + c * 16));
            *(uint4*)(dh + off) = *(const uint4*)(g_vh + gb + c * 8);
            *(uint4*)(dl + off) = *(const uint4*)(g_vl + gb + c * 8);
        }
    }
}

// ---------------------------------------------------------------------------
// Flash attention on mma.sync (hi/lo split), register-lean for 2 CTAs/SM.
// Q and P fragments are transient (reloaded/packed per ks) to stay <=128 regs.
// ---------------------------------------------------------------------------
__global__ __launch_bounds__(256, 2) void attn_mma()
{
    extern __shared__ char smem[];
    const uint32_t sb = smem_u32(smem);
    const int t = threadIdx.x, w = t >> 5, lane = t & 31;
    const int bh = blockIdx.y, qt = blockIdx.x;

    {
        const int row = t >> 1, half = t & 1;
        const size_t gb = ((size_t)bh * S_LEN + qt * 128 + row) * HD + half * 32;
#pragma unroll
        for (int c = 0; c < 4; c++) {
            const uint32_t off = SWZ((uint32_t)(row * 128 + half * 64 + c * 16));
            *(uint4*)(smem + SQ_H + off) = *(const uint4*)(g_qh + gb + c * 8);
            *(uint4*)(smem + SQ_L + off) = *(const uint4*)(g_ql + gb + c * 8);
        }
    }
    load_kv64(smem, bh, 0, 0, t);
    __syncthreads();

    const int qrow = w * 16 + (lane & 7) + ((lane >> 3) & 1) * 8;
    const int qcb  = ((lane >> 4) & 1) * 16;
    const int brow = (lane & 7) + ((lane >> 4) & 1) * 8;
    const int bcb  = ((lane >> 3) & 1) * 16;

    float o[8][4];
#pragma unroll
    for (int n = 0; n < 8; n++)
#pragma unroll
        for (int j = 0; j < 4; j++) o[n][j] = 0.0f;
    float m0 = -1e30f, m1 = -1e30f, l0 = 0.0f, l1 = 0.0f;

    for (int kt = 0; kt < NT64; kt++) {
        const int buf = kt & 1;
        if (kt > 0) __syncthreads();
        if (kt + 1 < NT64) load_kv64(smem, bh, kt + 1, buf ^ 1, t);

        float s[8][4];
#pragma unroll
        for (int n = 0; n < 8; n++)
#pragma unroll
            for (int j = 0; j < 4; j++) s[n][j] = 0.0f;

        const uint32_t kh_b = sb + SK + buf * 16384;
        const uint32_t kl_b = kh_b + 8192;
#pragma unroll
        for (int ks = 0; ks < 4; ks++) {
            uint32_t qh4[4], ql4[4];                 // transient Q fragments
            const uint32_t qoff = SWZ((uint32_t)(qrow * 128 + ks * 32 + qcb));
            ldmx4(qh4, sb + SQ_H + qoff);
            ldmx4(ql4, sb + SQ_L + qoff);
#pragma unroll
            for (int p = 0; p < 4; p++) {
                const uint32_t off = SWZ((uint32_t)((p * 16 + brow) * 128 + ks * 32 + bcb));
                uint32_t bh4[4], bl4[4];
                ldmx4(bh4, kh_b + off);
                ldmx4(bl4, kl_b + off);
                mma16816(s[2 * p],     qh4, bh4);
                mma16816(s[2 * p],     ql4, bh4);
                mma16816(s[2 * p],     qh4, bl4);
                mma16816(s[2 * p + 1], qh4, bh4 + 2);
                mma16816(s[2 * p + 1], ql4, bh4 + 2);
                mma16816(s[2 * p + 1], qh4, bl4 + 2);
            }
        }

        float mx0 = -1e30f, mx1 = -1e30f;
#pragma unroll
        for (int n = 0; n < 8; n++) {
            mx0 = fmaxf(mx0, fmaxf(s[n][0], s[n][1]));
            mx1 = fmaxf(mx1, fmaxf(s[n][2], s[n][3]));
        }
        mx0 = fmaxf(mx0, __shfl_xor_sync(0xffffffffu, mx0, 1));
        mx0 = fmaxf(mx0, __shfl_xor_sync(0xffffffffu, mx0, 2));
        mx1 = fmaxf(mx1, __shfl_xor_sync(0xffffffffu, mx1, 1));
        mx1 = fmaxf(mx1, __shfl_xor_sync(0xffffffffu, mx1, 2));
        const float m0n = fmaxf(m0, mx0), m1n = fmaxf(m1, mx1);
        const float a0 = ex2(m0 - m0n), a1 = ex2(m1 - m1n);
        m0 = m0n; m1 = m1n;

        float s0 = 0.0f, s1 = 0.0f;
#pragma unroll
        for (int n = 0; n < 8; n++) {
            s[n][0] = ex2(s[n][0] - m0n); s[n][1] = ex2(s[n][1] - m0n);
            s[n][2] = ex2(s[n][2] - m1n); s[n][3] = ex2(s[n][3] - m1n);
            s0 += s[n][0] + s[n][1];
            s1 += s[n][2] + s[n][3];
        }
        s0 += __shfl_xor_sync(0xffffffffu, s0, 1);
        s0 += __shfl_xor_sync(0xffffffffu, s0, 2);
        s1 += __shfl_xor_sync(0xffffffffu, s1, 1);
        s1 += __shfl_xor_sync(0xffffffffu, s1, 2);
        l0 = l0 * a0 + s0;
        l1 = l1 * a1 + s1;

#pragma unroll
        for (int n = 0; n < 8; n++) {
            o[n][0] *= a0; o[n][1] *= a0; o[n][2] *= a1; o[n][3] *= a1;
        }

        // ---- fused pack + PV (transient P fragments per ks) ----
        const uint32_t vh_b = sb + SV + buf * 16384;
        const uint32_t vl_b = vh_b + 8192;
#pragma unroll
        for (int ks = 0; ks < 4; ks++) {
            uint32_t ph4[4], pl4[4];
            split_pack(s[2 * ks][0],     s[2 * ks][1],     ph4[0], pl4[0]);
            split_pack(s[2 * ks][2],     s[2 * ks][3],     ph4[1], pl4[1]);
            split_pack(s[2 * ks + 1][0], s[2 * ks + 1][1], ph4[2], pl4[2]);
            split_pack(s[2 * ks + 1][2], s[2 * ks + 1][3], ph4[3], pl4[3]);
#pragma unroll
            for (int p = 0; p < 4; p++) {
                const uint32_t off = SWZ((uint32_t)((p * 16 + brow) * 128 + ks * 32 + bcb));
                uint32_t bh4[4], bl4[4];
                ldmx4(bh4, vh_b + off);
                ldmx4(bl4, vl_b + off);
                mma16816(o[2 * p],     ph4, bh4);
                mma16816(o[2 * p],     pl4, bh4);
                mma16816(o[2 * p],     ph4, bl4);
                mma16816(o[2 * p + 1], ph4, bh4 + 2);
                mma16816(o[2 * p + 1], pl4, bh4 + 2);
                mma16816(o[2 * p + 1], ph4, bl4 + 2);
            }
        }
    }

    const float inv0 = 1.0f / l0, inv1 = 1.0f / l1;
    const int b_ = bh >> 3, h_ = bh & 7;
    const int r0 = qt * 128 + w * 16 + (lane >> 2);
    const int cb = h_ * 64 + 2 * (lane & 3);
#pragma unroll
    for (int n = 0; n < 8; n++) {
        uint32_t hp, lp;
        const size_t i0 = ((size_t)r0 * B_SZ + b_) * E_DIM + cb + n * 8;
        const size_t i1 = ((size_t)(r0 + 8) * B_SZ + b_) * E_DIM + cb + n * 8;
        split_pack(o[n][0] * inv0, o[n][1] * inv0, hp, lp);
        *(uint32_t*)(g_ch + i0) = hp; *(uint32_t*)(g_cl + i0) = lp;
        split_pack(o[n][2] * inv1, o[n][3] * inv1, hp, lp);
        *(uint32_t*)(g_ch + i1) = hp; *(uint32_t*)(g_cl + i1) = lp;
    }
}

extern "C" void kernel_launch(void* const* d_in, const int* in_sizes, int n_in,
                              void* d_out, int out_size)
{
    const float* query = (const float*)d_in[0];
    const float* key   = (const float*)d_in[1];
    const float* value = (const float*)d_in[2];
    const float* in_w  = (const float*)d_in[3];
    const float* in_b  = (const float*)d_in[4];
    const float* out_w = (const float*)d_in[5];
    const float* out_b = (const float*)d_in[6];
    float* out = (float*)d_out;

    static bool attr_set = false;
    if (!attr_set) {
        cudaFuncSetAttribute(attn_mma, cudaFuncAttributeMaxDynamicSharedMemorySize, SMEM_BIG);
        cudaFuncSetAttribute(gemm_mma, cudaFuncAttributeMaxDynamicSharedMemorySize, SMEM_BIG);
        attr_set = true;
    }

    cvt_kernel<<<dim3(1024, 3), 256>>>(query, key, value, M_ROWS * E_DIM / 4, 0);
    cvt_kernel<<<dim3(256, 3), 256>>>(in_w, in_w + 2 * E_DIM * E_DIM, out_w,
                                      E_DIM * E_DIM / 4, 1);

    gemm_mma<<<dim3(M_ROWS / 128, E_DIM / 64, 3), 256, SMEM_BIG>>>(in_b, out_b, out, 1);

    attn_mma<<<dim3(S_LEN / 128, NBH), 256, SMEM_BIG>>>();

    gemm_mma<<<dim3(M_ROWS / 128, E_DIM / 64, 1), 256, SMEM_BIG>>>(in_b, out_b, out, 0);
}

// round 11
// speedup vs baseline: 4.0442x; 1.0132x over previous
#include <cuda_runtime.h>
#include <cuda_bf16.h>
#include <cstdint>
#include <math.h>

#define S_LEN 2048
#define B_SZ  4
#define E_DIM 512
#define H_NUM 8
#define HD    64
#define M_ROWS (S_LEN * B_SZ)
#define NBH   (B_SZ * H_NUM)
#define NT64  (S_LEN / 64)

// ---------------- scratch ----------------------------------------------------
__device__ __align__(16) __nv_bfloat16 g_xqh[M_ROWS * E_DIM];
__device__ __align__(16) __nv_bfloat16 g_xql[M_ROWS * E_DIM];
__device__ __align__(16) __nv_bfloat16 g_xkh[M_ROWS * E_DIM];
__device__ __align__(16) __nv_bfloat16 g_xkl[M_ROWS * E_DIM];
__device__ __align__(16) __nv_bfloat16 g_xvh[M_ROWS * E_DIM];
__device__ __align__(16) __nv_bfloat16 g_xvl[M_ROWS * E_DIM];
__device__ __align__(16) __nv_bfloat16 g_wqkh[E_DIM * E_DIM];
__device__ __align__(16) __nv_bfloat16 g_wqkl[E_DIM * E_DIM];
__device__ __align__(16) __nv_bfloat16 g_wvh[E_DIM * E_DIM];
__device__ __align__(16) __nv_bfloat16 g_wvl[E_DIM * E_DIM];
__device__ __align__(16) __nv_bfloat16 g_woh[E_DIM * E_DIM];
__device__ __align__(16) __nv_bfloat16 g_wol[E_DIM * E_DIM];
__device__ __align__(16) __nv_bfloat16 g_qh[NBH * S_LEN * HD];  // [bh][s][d]
__device__ __align__(16) __nv_bfloat16 g_ql[NBH * S_LEN * HD];
__device__ __align__(16) __nv_bfloat16 g_kh[NBH * S_LEN * HD];  // [bh][s][d]
__device__ __align__(16) __nv_bfloat16 g_kl[NBH * S_LEN * HD];
__device__ __align__(16) __nv_bfloat16 g_vh[NBH * S_LEN * HD];  // [bh][d][s]
__device__ __align__(16) __nv_bfloat16 g_vl[NBH * S_LEN * HD];
__device__ __align__(16) __nv_bfloat16 g_ch[M_ROWS * E_DIM];
__device__ __align__(16) __nv_bfloat16 g_cl[M_ROWS * E_DIM];

// ---------------- helpers -----------------------------------------------------
__device__ __forceinline__ uint32_t smem_u32(const void* p) {
    uint32_t a;
    asm("{ .reg .u64 t; cvta.to.shared.u64 t, %1; cvt.u32.u64 %0, t; }" : "=r"(a) : "l"(p));
    return a;
}
__device__ __forceinline__ float ex2(float x) {
    float y; asm("ex2.approx.f32 %0, %1;" : "=f"(y) : "f"(x)); return y;
}
__device__ __forceinline__ void ldmx4(uint32_t* r, uint32_t addr) {
    asm volatile("ldmatrix.sync.aligned.m8n8.x4.shared.b16 {%0,%1,%2,%3}, [%4];"
                 : "=r"(r[0]), "=r"(r[1]), "=r"(r[2]), "=r"(r[3]) : "r"(addr));
}
__device__ __forceinline__ void mma16816(float* d, const uint32_t* a, const uint32_t* b) {
    asm volatile("mma.sync.aligned.m16n8k16.row.col.f32.bf16.bf16.f32 "
                 "{%0,%1,%2,%3}, {%4,%5,%6,%7}, {%8,%9}, {%0,%1,%2,%3};"
                 : "+f"(d[0]), "+f"(d[1]), "+f"(d[2]), "+f"(d[3])
                 : "r"(a[0]), "r"(a[1]), "r"(a[2]), "r"(a[3]), "r"(b[0]), "r"(b[1]));
}
// lean split: hi = RN-bf16x2(v), lo = RN-bf16x2(v - hi). 6 instructions.
__device__ __forceinline__ void split_pack(float v0, float v1, uint32_t& hp, uint32_t& lp) {
    asm("cvt.rn.bf16x2.f32 %0, %1, %2;" : "=r"(hp) : "f"(v1), "f"(v0));
    const float h0 = __uint_as_float(hp << 16);
    const float h1 = __uint_as_float(hp & 0xffff0000u);
    const float l0 = v0 - h0, l1 = v1 - h1;
    asm("cvt.rn.bf16x2.f32 %0, %1, %2;" : "=r"(lp) : "f"(l1), "f"(l0));
}
#define SWZ(x) ((x) ^ (((x) >> 3) & 0x70))
#define SMEM_BIG 98304

// ---------------------------------------------------------------------------
// Elementwise fp32 -> bf16 hi/lo conversion.
// ---------------------------------------------------------------------------
__global__ void cvt_kernel(const float* __restrict__ s0, const float* __restrict__ s1,
                           const float* __restrict__ s2, int n4, int wsel)
{
    const int z = blockIdx.y;
    const float* src = (z == 0) ? s0 : (z == 1) ? s1 : s2;
    __nv_bfloat16* dh; __nv_bfloat16* dl;
    if (!wsel) { dh = (z == 0) ? g_xqh : (z == 1) ? g_xkh : g_xvh;
                 dl = (z == 0) ? g_xql : (z == 1) ? g_xkl : g_xvl; }
    else       { dh = (z == 0) ? g_wqkh : (z == 1) ? g_wvh : g_woh;
                 dl = (z == 0) ? g_wqkl : (z == 1) ? g_wvl : g_wol; }

    for (int i = blockIdx.x * blockDim.x + threadIdx.x; i < n4; i += gridDim.x * blockDim.x) {
        float4 v = ((const float4*)src)[i];
        uint32_t h0, l0, h1, l1;
        split_pack(v.x, v.y, h0, l0);
        split_pack(v.z, v.w, h1, l1);
        ((uint2*)dh)[i] = make_uint2(h0, h1);
        ((uint2*)dl)[i] = make_uint2(l0, l1);
    }
}

// ---------------------------------------------------------------------------
// mma.sync GEMM: C[M,N] = A[M,K] @ B[N,K]^T, hi/lo split (3 terms).
// 2 CTAs/SM (regs capped at 128, smem 96KB x2 = 192KB <= 228KB).
// ---------------------------------------------------------------------------
__global__ __launch_bounds__(256, 2) void gemm_mma(
    const float* __restrict__ in_b, const float* __restrict__ out_b,
    float* __restrict__ outp, int qkv)
{
    extern __shared__ char smem[];
    const uint32_t sb = smem_u32(smem);
    const int mode = qkv ? blockIdx.z : 3;

    const __nv_bfloat16 *Ah, *Al, *Bh, *Bl;
    const float* bias;
    switch (mode) {
        case 0:  Ah = g_xqh; Al = g_xql; Bh = g_wqkh; Bl = g_wqkl; bias = in_b; break;
        case 1:  Ah = g_xkh; Al = g_xkl; Bh = g_wqkh; Bl = g_wqkl; bias = in_b; break;
        case 2:  Ah = g_xvh; Al = g_xvl; Bh = g_wvh;  Bl = g_wvl;  bias = in_b + 2 * E_DIM; break;
        default: Ah = g_ch;  Al = g_cl;  Bh = g_woh;  Bl = g_wol;  bias = out_b; break;
    }
    const float scale = (mode == 0) ? 0.125f * 1.44269504088896340736f : 1.0f;

    const int mBase = blockIdx.x * 128, nBase = blockIdx.y * 64;
    const int t = threadIdx.x, w = t >> 5, lane = t & 31;
    const int wm = w & 3, wn = w >> 2;

    auto load_tile = [&](int buf, int k0) {
        char* da = smem + buf * 49152;
        {
            const int row = t >> 1, half = t & 1;
            const size_t gb = (size_t)(mBase + row) * E_DIM + k0 + half * 32;
#pragma unroll
            for (int i = 0; i < 4; i++) {
                const uint32_t off = SWZ((uint32_t)(row * 128 + half * 64 + i * 16));
                *(uint4*)(da + off)         = *(const uint4*)(Ah + gb + i * 8);
                *(uint4*)(da + 16384 + off) = *(const uint4*)(Al + gb + i * 8);
            }
        }
        {
            const int row = t >> 2, q = t & 3;
            const size_t gb = (size_t)(nBase + row) * E_DIM + k0;
            char* db = da + 32768;
#pragma unroll
            for (int i = 0; i < 2; i++) {
                const int j = q + i * 4;
                const uint32_t off = SWZ((uint32_t)(row * 128 + j * 16));
                *(uint4*)(db + off)        = *(const uint4*)(Bh + gb + j * 8);
                *(uint4*)(db + 8192 + off) = *(const uint4*)(Bl + gb + j * 8);
            }
        }
    };

    load_tile(0, 0);
    __syncthreads();

    float acc[2][4][4];
#pragma unroll
    for (int a = 0; a < 2; a++)
#pragma unroll
        for (int b = 0; b < 4; b++)
#pragma unroll
            for (int c = 0; c < 4; c++) acc[a][b][c] = 0.0f;

    const int arow = wm * 32 + (lane & 7) + ((lane >> 3) & 1) * 8;
    const int acb  = ((lane >> 4) & 1) * 16;
    const int brow = wn * 32 + (lane & 7) + ((lane >> 4) & 1) * 8;
    const int bcb  = ((lane >> 3) & 1) * 16;

    for (int kc = 0; kc < E_DIM / 64; kc++) {
        const int buf = kc & 1;
        if (kc + 1 < E_DIM / 64) load_tile(buf ^ 1, (kc + 1) * 64);

        const uint32_t AH = sb + buf * 49152;
        const uint32_t AL = AH + 16384;
        const uint32_t BH = AH + 32768;
        const uint32_t BL = BH + 8192;
#pragma unroll
        for (int ks = 0; ks < 4; ks++) {
            uint32_t ah0[4], al0[4], ah1[4], al1[4];
            ldmx4(ah0, AH + SWZ((uint32_t)(arow * 128 + ks * 32 + acb)));
            ldmx4(ah1, AH + SWZ((uint32_t)((arow + 16) * 128 + ks * 32 + acb)));
            ldmx4(al0, AL + SWZ((uint32_t)(arow * 128 + ks * 32 + acb)));
            ldmx4(al1, AL + SWZ((uint32_t)((arow + 16) * 128 + ks * 32 + acb)));
#pragma unroll
            for (int n2 = 0; n2 < 2; n2++) {
                uint32_t bh4[4], bl4[4];
                const uint32_t boff = SWZ((uint32_t)((brow + n2 * 16) * 128 + ks * 32 + bcb));
                ldmx4(bh4, BH + boff);
                ldmx4(bl4, BL + boff);
#pragma unroll
                for (int h = 0; h < 2; h++) {
                    float* d0 = acc[0][n2 * 2 + h];
                    float* d1 = acc[1][n2 * 2 + h];
                    mma16816(d0, ah0, bh4 + 2 * h);
                    mma16816(d0, al0, bh4 + 2 * h);
                    mma16816(d0, ah0, bl4 + 2 * h);
                    mma16816(d1, ah1, bh4 + 2 * h);
                    mma16816(d1, al1, bh4 + 2 * h);
                    mma16816(d1, ah1, bl4 + 2 * h);
                }
            }
        }
        __syncthreads();
    }

#pragma unroll
    for (int mi = 0; mi < 2; mi++) {
#pragma unroll
        for (int nj = 0; nj < 4; nj++) {
            const int r0 = mBase + wm * 32 + mi * 16 + (lane >> 2);
            const int c  = nBase + wn * 32 + nj * 8 + 2 * (lane & 3);
            const float2 bv = *(const float2*)(bias + c);
            float v00 = (acc[mi][nj][0] + bv.x) * scale;
            float v01 = (acc[mi][nj][1] + bv.y) * scale;
            float v10 = (acc[mi][nj][2] + bv.x) * scale;
            float v11 = (acc[mi][nj][3] + bv.y) * scale;
            if (mode == 3) {
                *(float2*)(outp + (size_t)r0 * E_DIM + c)       = make_float2(v00, v01);
                *(float2*)(outp + (size_t)(r0 + 8) * E_DIM + c) = make_float2(v10, v11);
            } else {
                const int h_ = c >> 6, d = c & 63;
                const int s0 = r0 >> 2, b0 = r0 & 3;
                const int s1 = (r0 + 8) >> 2, b1 = (r0 + 8) & 3;
                uint32_t hp0, lp0, hp1, lp1;
                split_pack(v00, v01, hp0, lp0);
                split_pack(v10, v11, hp1, lp1);
                if (mode < 2) {
                    __nv_bfloat16* oh = (mode == 0) ? g_qh : g_kh;
                    __nv_bfloat16* ol = (mode == 0) ? g_ql : g_kl;
                    const size_t a0 = ((size_t)(b0 * H_NUM + h_) * S_LEN + s0) * HD + d;
                    const size_t a1 = ((size_t)(b1 * H_NUM + h_) * S_LEN + s1) * HD + d;
                    *(uint32_t*)(oh + a0) = hp0; *(uint32_t*)(ol + a0) = lp0;
                    *(uint32_t*)(oh + a1) = hp1; *(uint32_t*)(ol + a1) = lp1;
                } else {
                    const size_t base0 = ((size_t)(b0 * H_NUM + h_) * HD + d) * S_LEN + s0;
                    const size_t base1 = ((size_t)(b1 * H_NUM + h_) * HD + d) * S_LEN + s1;
                    g_vh[base0] = __ushort_as_bfloat16((uint16_t)hp0);
                    g_vh[base0 + S_LEN] = __ushort_as_bfloat16((uint16_t)(hp0 >> 16));
                    g_vl[base0] = __ushort_as_bfloat16((uint16_t)lp0);
                    g_vl[base0 + S_LEN] = __ushort_as_bfloat16((uint16_t)(lp0 >> 16));
                    g_vh[base1] = __ushort_as_bfloat16((uint16_t)hp1);
                    g_vh[base1 + S_LEN] = __ushort_as_bfloat16((uint16_t)(hp1 >> 16));
                    g_vl[base1] = __ushort_as_bfloat16((uint16_t)lp1);
                    g_vl[base1 + S_LEN] = __ushort_as_bfloat16((uint16_t)(lp1 >> 16));
                }
            }
        }
    }
}

// ---------------------------------------------------------------------------
// K/V 64-key tile -> smem (SW128-swizzled 128B rows).
// ---------------------------------------------------------------------------
#define SQ_H 0
#define SQ_L 16384
#define SK   32768
#define SV   65536

__device__ __forceinline__ void load_kv64(char* smem, int bh, int kt, int buf, int t)
{
    const int row = t >> 2, c0 = t & 3;
    {
        const size_t gb = ((size_t)bh * S_LEN + kt * 64 + row) * HD;
        char* dh = smem + SK + buf * 16384;
        char* dl = dh + 8192;
#pragma unroll
        for (int i = 0; i < 2; i++) {
            const int c = c0 + i * 4;
            const uint32_t off = SWZ((uint32_t)(row * 128 + c * 16));
            *(uint4*)(dh + off) = *(const uint4*)(g_kh + gb + c * 8);
            *(uint4*)(dl + off) = *(const uint4*)(g_kl + gb + c * 8);
        }
    }
    {
        const size_t gb = ((size_t)bh * HD + row) * S_LEN + kt * 64;
        char* dh = smem + SV + buf * 16384;
        char* dl = dh + 8192;
#pragma unroll
        for (int i = 0; i < 2; i++) {
            const int c = c0 + i * 4;
            const uint32_t off = SWZ((uint32_t)(row * 128 + c * 16));
            *(uint4*)(dh + off) = *(const uint4*)(g_vh + gb + c * 8);
            *(uint4*)(dl + off) = *(const uint4*)(g_vl + gb + c * 8);
        }
    }
}

// ---------------------------------------------------------------------------
// Flash attention on mma.sync (hi/lo split), register-lean for 2 CTAs/SM.
// ---------------------------------------------------------------------------
__global__ __launch_bounds__(256, 2) void attn_mma()
{
    extern __shared__ char smem[];
    const uint32_t sb = smem_u32(smem);
    const int t = threadIdx.x, w = t >> 5, lane = t & 31;
    const int bh = blockIdx.y, qt = blockIdx.x;

    {
        const int row = t >> 1, half = t & 1;
        const size_t gb = ((size_t)bh * S_LEN + qt * 128 + row) * HD + half * 32;
#pragma unroll
        for (int c = 0; c < 4; c++) {
            const uint32_t off = SWZ((uint32_t)(row * 128 + half * 64 + c * 16));
            *(uint4*)(smem + SQ_H + off) = *(const uint4*)(g_qh + gb + c * 8);
            *(uint4*)(smem + SQ_L + off) = *(const uint4*)(g_ql + gb + c * 8);
        }
    }
    load_kv64(smem, bh, 0, 0, t);
    __syncthreads();

    const int qrow = w * 16 + (lane & 7) + ((lane >> 3) & 1) * 8;
    const int qcb  = ((lane >> 4) & 1) * 16;
    const int brow = (lane & 7) + ((lane >> 4) & 1) * 8;
    const int bcb  = ((lane >> 3) & 1) * 16;

    float o[8][4];
#pragma unroll
    for (int n = 0; n < 8; n++)
#pragma unroll
        for (int j = 0; j < 4; j++) o[n][j] = 0.0f;
    float m0 = -1e30f, m1 = -1e30f, l0 = 0.0f, l1 = 0.0f;

    for (int kt = 0; kt < NT64; kt++) {
        const int buf = kt & 1;
        if (kt > 0) __syncthreads();
        if (kt + 1 < NT64) load_kv64(smem, bh, kt + 1, buf ^ 1, t);

        float s[8][4];
#pragma unroll
        for (int n = 0; n < 8; n++)
#pragma unroll
            for (int j = 0; j < 4; j++) s[n][j] = 0.0f;

        const uint32_t kh_b = sb + SK + buf * 16384;
        const uint32_t kl_b = kh_b + 8192;
#pragma unroll
        for (int ks = 0; ks < 4; ks++) {
            uint32_t qh4[4], ql4[4];
            const uint32_t qoff = SWZ((uint32_t)(qrow * 128 + ks * 32 + qcb));
            ldmx4(qh4, sb + SQ_H + qoff);
            ldmx4(ql4, sb + SQ_L + qoff);
#pragma unroll
            for (int p = 0; p < 4; p++) {
                const uint32_t off = SWZ((uint32_t)((p * 16 + brow) * 128 + ks * 32 + bcb));
                uint32_t bh4[4], bl4[4];
                ldmx4(bh4, kh_b + off);
                ldmx4(bl4, kl_b + off);
                mma16816(s[2 * p],     qh4, bh4);
                mma16816(s[2 * p],     ql4, bh4);
                mma16816(s[2 * p],     qh4, bl4);
                mma16816(s[2 * p + 1], qh4, bh4 + 2);
                mma16816(s[2 * p + 1], ql4, bh4 + 2);
                mma16816(s[2 * p + 1], qh4, bl4 + 2);
            }
        }

        float mx0 = -1e30f, mx1 = -1e30f;
#pragma unroll
        for (int n = 0; n < 8; n++) {
            mx0 = fmaxf(mx0, fmaxf(s[n][0], s[n][1]));
            mx1 = fmaxf(mx1, fmaxf(s[n][2], s[n][3]));
        }
        mx0 = fmaxf(mx0, __shfl_xor_sync(0xffffffffu, mx0, 1));
        mx0 = fmaxf(mx0, __shfl_xor_sync(0xffffffffu, mx0, 2));
        mx1 = fmaxf(mx1, __shfl_xor_sync(0xffffffffu, mx1, 1));
        mx1 = fmaxf(mx1, __shfl_xor_sync(0xffffffffu, mx1, 2));
        const float m0n = fmaxf(m0, mx0), m1n = fmaxf(m1, mx1);
        const float a0 = ex2(m0 - m0n), a1 = ex2(m1 - m1n);
        m0 = m0n; m1 = m1n;

        float s0 = 0.0f, s1 = 0.0f;
#pragma unroll
        for (int n = 0; n < 8; n++) {
            s[n][0] = ex2(s[n][0] - m0n); s[n][1] = ex2(s[n][1] - m0n);
            s[n][2] = ex2(s[n][2] - m1n); s[n][3] = ex2(s[n][3] - m1n);
            s0 += s[n][0] + s[n][1];
            s1 += s[n][2] + s[n][3];
        }
        s0 += __shfl_xor_sync(0xffffffffu, s0, 1);
        s0 += __shfl_xor_sync(0xffffffffu, s0, 2);
        s1 += __shfl_xor_sync(0xffffffffu, s1, 1);
        s1 += __shfl_xor_sync(0xffffffffu, s1, 2);
        l0 = l0 * a0 + s0;
        l1 = l1 * a1 + s1;

#pragma unroll
        for (int n = 0; n < 8; n++) {
            o[n][0] *= a0; o[n][1] *= a0; o[n][2] *= a1; o[n][3] *= a1;
        }

        const uint32_t vh_b = sb + SV + buf * 16384;
        const uint32_t vl_b = vh_b + 8192;
#pragma unroll
        for (int ks = 0; ks < 4; ks++) {
            uint32_t ph4[4], pl4[4];
            split_pack(s[2 * ks][0],     s[2 * ks][1],     ph4[0], pl4[0]);
            split_pack(s[2 * ks][2],     s[2 * ks][3],     ph4[1], pl4[1]);
            split_pack(s[2 * ks + 1][0], s[2 * ks + 1][1], ph4[2], pl4[2]);
            split_pack(s[2 * ks + 1][2], s[2 * ks + 1][3], ph4[3], pl4[3]);
#pragma unroll
            for (int p = 0; p < 4; p++) {
                const uint32_t off = SWZ((uint32_t)((p * 16 + brow) * 128 + ks * 32 + bcb));
                uint32_t bh4[4], bl4[4];
                ldmx4(bh4, vh_b + off);
                ldmx4(bl4, vl_b + off);
                mma16816(o[2 * p],     ph4, bh4);
                mma16816(o[2 * p],     pl4, bh4);
                mma16816(o[2 * p],     ph4, bl4);
                mma16816(o[2 * p + 1], ph4, bh4 + 2);
                mma16816(o[2 * p + 1], pl4, bh4 + 2);
                mma16816(o[2 * p + 1], ph4, bl4 + 2);
            }
        }
    }

    const float inv0 = 1.0f / l0, inv1 = 1.0f / l1;
    const int b_ = bh >> 3, h_ = bh & 7;
    const int r0 = qt * 128 + w * 16 + (lane >> 2);
    const int cb = h_ * 64 + 2 * (lane & 3);
#pragma unroll
    for (int n = 0; n < 8; n++) {
        uint32_t hp, lp;
        const size_t i0 = ((size_t)r0 * B_SZ + b_) * E_DIM + cb + n * 8;
        const size_t i1 = ((size_t)(r0 + 8) * B_SZ + b_) * E_DIM + cb + n * 8;
        split_pack(o[n][0] * inv0, o[n][1] * inv0, hp, lp);
        *(uint32_t*)(g_ch + i0) = hp; *(uint32_t*)(g_cl + i0) = lp;
        split_pack(o[n][2] * inv1, o[n][3] * inv1, hp, lp);
        *(uint32_t*)(g_ch + i1) = hp; *(uint32_t*)(g_cl + i1) = lp;
    }
}

extern "C" void kernel_launch(void* const* d_in, const int* in_sizes, int n_in,
                              void* d_out, int out_size)
{
    const float* query = (const float*)d_in[0];
    const float* key   = (const float*)d_in[1];
    const float* value = (const float*)d_in[2];
    const float* in_w  = (const float*)d_in[3];
    const float* in_b  = (const float*)d_in[4];
    const float* out_w = (const float*)d_in[5];
    const float* out_b = (const float*)d_in[6];
    float* out = (float*)d_out;

    static bool attr_set = false;
    if (!attr_set) {
        cudaFuncSetAttribute(attn_mma, cudaFuncAttributeMaxDynamicSharedMemorySize, SMEM_BIG);
        cudaFuncSetAttribute(gemm_mma, cudaFuncAttributeMaxDynamicSharedMemorySize, SMEM_BIG);
        attr_set = true;
    }

    cvt_kernel<<<dim3(1024, 3), 256>>>(query, key, value, M_ROWS * E_DIM / 4, 0);
    cvt_kernel<<<dim3(256, 3), 256>>>(in_w, in_w + 2 * E_DIM * E_DIM, out_w,
                                      E_DIM * E_DIM / 4, 1);

    gemm_mma<<<dim3(M_ROWS / 128, E_DIM / 64, 3), 256, SMEM_BIG>>>(in_b, out_b, out, 1);

    attn_mma<<<dim3(S_LEN / 128, NBH), 256, SMEM_BIG>>>();

    gemm_mma<<<dim3(M_ROWS / 128, E_DIM / 64, 1), 256, SMEM_BIG>>>(in_b, out_b, out, 0);
}